// round 5
// baseline (speedup 1.0000x reference)
#include <cuda_runtime.h>

// Problem constants
#define NB    16
#define N_TOT 16384
#define PPT   128
#define FEAT  256
#define EMB   100
#define OUTW  200

typedef unsigned long long u64;

__device__ __forceinline__ u64 pk2(float lo, float hi) {
    u64 r; asm("mov.b64 %0, {%1,%2};" : "=l"(r) : "f"(lo), "f"(hi)); return r;
}
__device__ __forceinline__ void fma2(u64& a, u64 x, u64 w) {
    asm("fma.rn.f32x2 %0, %1, %2, %0;" : "+l"(a) : "l"(x), "l"(w));
}
__device__ __forceinline__ float2 up2(u64 v) {
    float2 f; asm("mov.b64 {%0,%1}, %2;" : "=f"(f.x), "=f"(f.y) : "l"(v)); return f;
}

// Bank-skewed row indexing (+4 words per 8-row group).
#define H1I(p) ((p) * 68  + ((p) >> 3) * 4)
#define H2I(p) ((p) * 132 + ((p) >> 3) * 4)

// ---------------------------------------------------------------------------
// Point branch: block = one object, 128 threads, 4 groups of 32 points.
// Thread tile (GEMMs): 4 pts (mg=lane>>2, 8 groups) x 8/16 cols (ng=lane&3).
//   layer2 warp w owns cols [w*32, w*32+32)  -> thread: 4 pts x 8 cols
//   layer3 warp w owns cols [w*64, w*64+64)  -> thread: 4 pts x 16 cols
// Inner math: packed fma.rn.f32x2 (col dimension paired).
// ---------------------------------------------------------------------------
__global__ __launch_bounds__(128, 3) void point_branch_kernel(
    const float* __restrict__ pts,   // (N_TOT, 128, 3)
    const float* __restrict__ w1,    // (3, 64)
    const float* __restrict__ b1,    // (64)
    const float* __restrict__ w2,    // (64, 128)
    const float* __restrict__ b2,    // (128)
    const float* __restrict__ w3,    // (128, 256)
    const float* __restrict__ b3,    // (256)
    const float* __restrict__ oew,   // (256, 100)
    const float* __restrict__ oeb,   // (100)
    float* __restrict__ out)         // (N_TOT, 200)
{
    __shared__ float h1s[2200];      // 32 x 64 skewed
    __shared__ float h2s[4240];      // 32 x 128 skewed
    __shared__ float feat_s[256];

    const int n    = blockIdx.x;
    const int t    = threadIdx.x;
    const int w    = t >> 5;         // warp id 0..3
    const int lane = t & 31;
    const int mg   = lane >> 2;      // 8 point groups of 4
    const int ng   = lane & 3;       // 4 column subtiles

    const int c2 = w * 32 + ng * 8;   // layer-2 col base (8 cols)
    const int c3 = w * 64 + ng * 16;  // layer-3 col base (16 cols)

    float runmax[16];
#pragma unroll
    for (int j = 0; j < 16; ++j) runmax[j] = -3.0e38f;

    const ulonglong2 b2a = __ldg((const ulonglong2*)(b2 + c2));
    const ulonglong2 b2b = __ldg((const ulonglong2*)(b2 + c2 + 4));

#pragma unroll 1
    for (int pg = 0; pg < 4; ++pg) {
        __syncthreads();  // prior-iteration h1/h2 readers done

        // ---- layer 1: 32 points; thread (pl, jq) computes 16 outputs
        {
            const int pl = t & 31;
            const int j0 = (t >> 5) * 16;
            const size_t pb = ((size_t)n * PPT + (size_t)pg * 32 + pl) * 3;
            const float x = pts[pb + 0];
            const float y = pts[pb + 1];
            const float z = pts[pb + 2];
            const int hb = H1I(pl);
#pragma unroll
            for (int j = 0; j < 16; j += 4) {
                const int jj = j0 + j;
                float4 v;
                v.x = fmaf(x, __ldg(w1 + jj + 0), fmaf(y, __ldg(w1 + 64 + jj + 0), fmaf(z, __ldg(w1 + 128 + jj + 0), __ldg(b1 + jj + 0))));
                v.y = fmaf(x, __ldg(w1 + jj + 1), fmaf(y, __ldg(w1 + 64 + jj + 1), fmaf(z, __ldg(w1 + 128 + jj + 1), __ldg(b1 + jj + 1))));
                v.z = fmaf(x, __ldg(w1 + jj + 2), fmaf(y, __ldg(w1 + 64 + jj + 2), fmaf(z, __ldg(w1 + 128 + jj + 2), __ldg(b1 + jj + 2))));
                v.w = fmaf(x, __ldg(w1 + jj + 3), fmaf(y, __ldg(w1 + 64 + jj + 3), fmaf(z, __ldg(w1 + 128 + jj + 3), __ldg(b1 + jj + 3))));
                v.x = fmaxf(v.x, 0.0f); v.y = fmaxf(v.y, 0.0f);
                v.z = fmaxf(v.z, 0.0f); v.w = fmaxf(v.w, 0.0f);
                *(float4*)&h1s[hb + jj] = v;
            }
        }
        __syncthreads();

        // ---- layer 2: thread tile 4 pts x 8 cols (cols c2..c2+8), f32x2
        {
            u64 acc[4][4];
#pragma unroll
            for (int i = 0; i < 4; ++i) {
                acc[i][0] = b2a.x; acc[i][1] = b2a.y;
                acc[i][2] = b2b.x; acc[i][3] = b2b.y;
            }
#pragma unroll 1
            for (int k = 0; k < 64; k += 4) {
                u64 s[4][4];
#pragma unroll
                for (int i = 0; i < 4; ++i) {
                    const float4 a = *(const float4*)&h1s[H1I(mg * 4 + i) + k];
                    s[i][0] = pk2(a.x, a.x); s[i][1] = pk2(a.y, a.y);
                    s[i][2] = pk2(a.z, a.z); s[i][3] = pk2(a.w, a.w);
                }
#pragma unroll
                for (int q = 0; q < 4; ++q) {
                    const float* wr = w2 + (size_t)(k + q) * 128 + c2;
                    const ulonglong2 wa = __ldg((const ulonglong2*)(wr));
                    const ulonglong2 wb = __ldg((const ulonglong2*)(wr + 4));
#pragma unroll
                    for (int i = 0; i < 4; ++i) {
                        fma2(acc[i][0], s[i][q], wa.x);
                        fma2(acc[i][1], s[i][q], wa.y);
                        fma2(acc[i][2], s[i][q], wb.x);
                        fma2(acc[i][3], s[i][q], wb.y);
                    }
                }
            }
#pragma unroll
            for (int i = 0; i < 4; ++i) {
                const int hb = H2I(mg * 4 + i) + c2;
                const float2 p0 = up2(acc[i][0]), p1 = up2(acc[i][1]);
                const float2 p2 = up2(acc[i][2]), p3 = up2(acc[i][3]);
                float4 v0, v1;
                v0.x = fmaxf(p0.x, 0.0f); v0.y = fmaxf(p0.y, 0.0f);
                v0.z = fmaxf(p1.x, 0.0f); v0.w = fmaxf(p1.y, 0.0f);
                v1.x = fmaxf(p2.x, 0.0f); v1.y = fmaxf(p2.y, 0.0f);
                v1.z = fmaxf(p3.x, 0.0f); v1.w = fmaxf(p3.y, 0.0f);
                *(float4*)&h2s[hb]     = v0;
                *(float4*)&h2s[hb + 4] = v1;
            }
        }
        __syncthreads();

        // ---- layer 3: thread tile 4 pts x 16 cols (cols c3..c3+16), f32x2,
        //      processed as two 8-col halves; max folded into registers.
        {
            u64 acc[4][8];
#pragma unroll
            for (int i = 0; i < 4; ++i)
#pragma unroll
                for (int o = 0; o < 8; ++o) acc[i][o] = 0ull;

#pragma unroll 1
            for (int k = 0; k < 128; k += 4) {
                u64 s[4][4];
#pragma unroll
                for (int i = 0; i < 4; ++i) {
                    const float4 a = *(const float4*)&h2s[H2I(mg * 4 + i) + k];
                    s[i][0] = pk2(a.x, a.x); s[i][1] = pk2(a.y, a.y);
                    s[i][2] = pk2(a.z, a.z); s[i][3] = pk2(a.w, a.w);
                }
                // half A: cols c3 .. c3+8
#pragma unroll
                for (int q = 0; q < 4; ++q) {
                    const float* wr = w3 + (size_t)(k + q) * 256 + c3;
                    const ulonglong2 wa = __ldg((const ulonglong2*)(wr));
                    const ulonglong2 wb = __ldg((const ulonglong2*)(wr + 4));
#pragma unroll
                    for (int i = 0; i < 4; ++i) {
                        fma2(acc[i][0], s[i][q], wa.x);
                        fma2(acc[i][1], s[i][q], wa.y);
                        fma2(acc[i][2], s[i][q], wb.x);
                        fma2(acc[i][3], s[i][q], wb.y);
                    }
                }
                // half B: cols c3+8 .. c3+16
#pragma unroll
                for (int q = 0; q < 4; ++q) {
                    const float* wr = w3 + (size_t)(k + q) * 256 + c3 + 8;
                    const ulonglong2 wa = __ldg((const ulonglong2*)(wr));
                    const ulonglong2 wb = __ldg((const ulonglong2*)(wr + 4));
#pragma unroll
                    for (int i = 0; i < 4; ++i) {
                        fma2(acc[i][4], s[i][q], wa.x);
                        fma2(acc[i][5], s[i][q], wa.y);
                        fma2(acc[i][6], s[i][q], wb.x);
                        fma2(acc[i][7], s[i][q], wb.y);
                    }
                }
            }
#pragma unroll
            for (int o = 0; o < 8; ++o) {
#pragma unroll
                for (int i = 0; i < 4; ++i) {
                    const float2 f = up2(acc[i][o]);
                    runmax[2 * o]     = fmaxf(runmax[2 * o],     f.x);
                    runmax[2 * o + 1] = fmaxf(runmax[2 * o + 1], f.y);
                }
            }
        }
    }

    // ---- reduce max across the 8 mg groups (same ng => same cols)
#pragma unroll
    for (int j = 0; j < 16; ++j) {
        float m = runmax[j];
        m = fmaxf(m, __shfl_xor_sync(0xffffffffu, m, 4));
        m = fmaxf(m, __shfl_xor_sync(0xffffffffu, m, 8));
        m = fmaxf(m, __shfl_xor_sync(0xffffffffu, m, 16));
        if (mg == 0) feat_s[c3 + j] = m + __ldg(b3 + c3 + j);
    }
    __syncthreads();

    // ---- pt_out = feat @ oe_w + oe_b (100 outputs)
    if (t < EMB) {
        float acc = __ldg(oeb + t);
#pragma unroll 4
        for (int k = 0; k < 256; k += 4) {
            const float4 f = *(const float4*)&feat_s[k];
            acc = fmaf(f.x, __ldg(oew + (size_t)(k + 0) * EMB + t), acc);
            acc = fmaf(f.y, __ldg(oew + (size_t)(k + 1) * EMB + t), acc);
            acc = fmaf(f.z, __ldg(oew + (size_t)(k + 2) * EMB + t), acc);
            acc = fmaf(f.w, __ldg(oew + (size_t)(k + 3) * EMB + t), acc);
        }
        out[(size_t)n * OUTW + EMB + t] = acc;
    }
}

// ---------------------------------------------------------------------------
// Node branch (unchanged, ~5% of runtime)
// ---------------------------------------------------------------------------
__global__ __launch_bounds__(256) void node_branch_kernel(
    const float* __restrict__ srcf,
    const float* __restrict__ reff,
    const void*  __restrict__ counts_raw,
    const float* __restrict__ w1,
    const float* __restrict__ b1,
    const float* __restrict__ w2,
    const float* __restrict__ b2,
    const float* __restrict__ sew,
    const float* __restrict__ seb,
    float* __restrict__ out)
{
    __shared__ float xs[8 * 260];
    __shared__ float hs[8 * 260];
    __shared__ int srow[8];
    __shared__ int sflag[8];

    const int t = threadIdx.x;
    const long long o0 = (long long)blockIdx.x * 8;

    if (t < 8) {
        const int* c32 = (const int*)counts_raw;
        const bool is64 = (c32[1] == 0 && c32[3] == 0);
        const long long o = o0 + t;
        long long cum = 0, ssum = 0, rsum = 0, idx = 0;
        int flag = 0;
        for (int b = 0; b < NB; ++b) {
            long long sc, rc;
            if (is64) {
                sc = ((const long long*)counts_raw)[2 * b];
                rc = ((const long long*)counts_raw)[2 * b + 1];
            } else {
                sc = c32[2 * b];
                rc = c32[2 * b + 1];
            }
            const long long tot = sc + rc;
            if (o < cum + tot) {
                const long long off = o - cum;
                if (off < sc) { flag = 0; idx = ssum + off; }
                else          { flag = 1; idx = rsum + (off - sc); }
                break;
            }
            cum += tot; ssum += sc; rsum += rc;
        }
        srow[t]  = (int)idx;
        sflag[t] = flag;
    }
    __syncthreads();

#pragma unroll
    for (int r = 0; r < 8; ++r) {
        const float* base = sflag[r] ? reff : srcf;
        xs[r * 260 + t] = base[(size_t)srow[r] * FEAT + t];
    }
    __syncthreads();

    float acc[8];

    {
        const float bv = __ldg(b1 + t);
#pragma unroll
        for (int r = 0; r < 8; ++r) acc[r] = bv;
#pragma unroll 1
        for (int k = 0; k < 256; k += 4) {
            const float w0 = __ldg(w1 + (size_t)(k + 0) * 256 + t);
            const float wq1 = __ldg(w1 + (size_t)(k + 1) * 256 + t);
            const float wq2 = __ldg(w1 + (size_t)(k + 2) * 256 + t);
            const float wq3 = __ldg(w1 + (size_t)(k + 3) * 256 + t);
#pragma unroll
            for (int r = 0; r < 8; ++r) {
                float4 xv = *(const float4*)&xs[r * 260 + k];
                acc[r] = fmaf(xv.x, w0, acc[r]);
                acc[r] = fmaf(xv.y, wq1, acc[r]);
                acc[r] = fmaf(xv.z, wq2, acc[r]);
                acc[r] = fmaf(xv.w, wq3, acc[r]);
            }
        }
#pragma unroll
        for (int r = 0; r < 8; ++r) hs[r * 260 + t] = fmaxf(acc[r], 0.0f);
    }
    __syncthreads();

    {
        const float bv = __ldg(b2 + t);
#pragma unroll
        for (int r = 0; r < 8; ++r) acc[r] = bv;
#pragma unroll 1
        for (int k = 0; k < 256; k += 4) {
            const float w0 = __ldg(w2 + (size_t)(k + 0) * 256 + t);
            const float wq1 = __ldg(w2 + (size_t)(k + 1) * 256 + t);
            const float wq2 = __ldg(w2 + (size_t)(k + 2) * 256 + t);
            const float wq3 = __ldg(w2 + (size_t)(k + 3) * 256 + t);
#pragma unroll
            for (int r = 0; r < 8; ++r) {
                float4 xv = *(const float4*)&hs[r * 260 + k];
                acc[r] = fmaf(xv.x, w0, acc[r]);
                acc[r] = fmaf(xv.y, wq1, acc[r]);
                acc[r] = fmaf(xv.z, wq2, acc[r]);
                acc[r] = fmaf(xv.w, wq3, acc[r]);
            }
        }
#pragma unroll
        for (int r = 0; r < 8; ++r) xs[r * 260 + t] = acc[r];
    }
    __syncthreads();

    if (t < EMB) {
        float accs[8];
        const float bv = __ldg(seb + t);
#pragma unroll
        for (int r = 0; r < 8; ++r) accs[r] = bv;
#pragma unroll 1
        for (int k = 0; k < 256; k += 4) {
            const float w0 = __ldg(sew + (size_t)(k + 0) * EMB + t);
            const float wq1 = __ldg(sew + (size_t)(k + 1) * EMB + t);
            const float wq2 = __ldg(sew + (size_t)(k + 2) * EMB + t);
            const float wq3 = __ldg(sew + (size_t)(k + 3) * EMB + t);
#pragma unroll
            for (int r = 0; r < 8; ++r) {
                float4 ev = *(const float4*)&xs[r * 260 + k];
                accs[r] = fmaf(ev.x, w0, accs[r]);
                accs[r] = fmaf(ev.y, wq1, accs[r]);
                accs[r] = fmaf(ev.z, wq2, accs[r]);
                accs[r] = fmaf(ev.w, wq3, accs[r]);
            }
        }
#pragma unroll
        for (int r = 0; r < 8; ++r)
            out[(size_t)(o0 + r) * OUTW + t] = accs[r];
    }
}

extern "C" void kernel_launch(void* const* d_in, const int* in_sizes, int n_in,
                              void* d_out, int out_size)
{
    const float* pts    = (const float*)d_in[0];
    const float* srcf   = (const float*)d_in[1];
    const float* reff   = (const float*)d_in[2];
    const void*  counts = d_in[3];
    const float* sg_w1  = (const float*)d_in[6];
    const float* sg_b1  = (const float*)d_in[7];
    const float* sg_w2  = (const float*)d_in[8];
    const float* sg_b2  = (const float*)d_in[9];
    const float* se_w   = (const float*)d_in[10];
    const float* se_b   = (const float*)d_in[11];
    const float* p_w1   = (const float*)d_in[12];
    const float* p_b1   = (const float*)d_in[13];
    const float* p_w2   = (const float*)d_in[14];
    const float* p_b2   = (const float*)d_in[15];
    const float* p_w3   = (const float*)d_in[16];
    const float* p_b3   = (const float*)d_in[17];
    const float* oe_w   = (const float*)d_in[18];
    const float* oe_b   = (const float*)d_in[19];
    float* out = (float*)d_out;

    node_branch_kernel<<<N_TOT / 8, 256>>>(srcf, reff, counts,
                                           sg_w1, sg_b1, sg_w2, sg_b2,
                                           se_w, se_b, out);
    point_branch_kernel<<<N_TOT, 128>>>(pts, p_w1, p_b1, p_w2, p_b2,
                                        p_w3, p_b3, oe_w, oe_b, out);
}

// round 7
// speedup vs baseline: 2.1338x; 2.1338x over previous
#include <cuda_runtime.h>
#include <cuda_bf16.h>
#include <stdint.h>

#define NB    16
#define N_TOT 16384
#define PPT   128
#define FEAT  256
#define EMB   100
#define OUTW  200

typedef unsigned long long u64;
typedef unsigned int u32;

// ---------------- f32x2 helpers (layers 1-2) ----------------
__device__ __forceinline__ u64 pk2(float lo, float hi) {
    u64 r; asm("mov.b64 %0, {%1,%2};" : "=l"(r) : "f"(lo), "f"(hi)); return r;
}
__device__ __forceinline__ void fma2(u64& a, u64 x, u64 w) {
    asm("fma.rn.f32x2 %0, %1, %2, %0;" : "+l"(a) : "l"(x), "l"(w));
}
__device__ __forceinline__ float2 up2(u64 v) {
    float2 f; asm("mov.b64 {%0,%1}, %2;" : "=f"(f.x), "=f"(f.y) : "l"(v)); return f;
}

// ---------------- bf16 split helper ----------------
__device__ __forceinline__ void split2(float x0, float x1, u32& hi, u32& lo) {
    __nv_bfloat16 h0 = __float2bfloat16(x0);
    __nv_bfloat16 h1 = __float2bfloat16(x1);
    __nv_bfloat16 l0 = __float2bfloat16(x0 - __bfloat162float(h0));
    __nv_bfloat16 l1 = __float2bfloat16(x1 - __bfloat162float(h1));
    __nv_bfloat162 hh = __halves2bfloat162(h0, h1);
    __nv_bfloat162 ll = __halves2bfloat162(l0, l1);
    hi = *(u32*)&hh; lo = *(u32*)&ll;
}

// ---------------- mma.sync m16n8k16 bf16 (portable ISA) ----------------
__device__ __forceinline__ void mma_bf16(float* c,
                                         u32 a0, u32 a1, u32 a2, u32 a3,
                                         u32 b0, u32 b1) {
    asm("mma.sync.aligned.m16n8k16.row.col.f32.bf16.bf16.f32 "
        "{%0,%1,%2,%3}, {%4,%5,%6,%7}, {%8,%9}, {%0,%1,%2,%3};"
        : "+f"(c[0]), "+f"(c[1]), "+f"(c[2]), "+f"(c[3])
        : "r"(a0), "r"(a1), "r"(a2), "r"(a3), "r"(b0), "r"(b1));
}

// Skewed h1 layout
#define H1I(p) ((p) * 68 + ((p) >> 3) * 4)
// A (h2 split) layout: [64 rows][68 u32 words], word w = bf16x2 of cols (2w, 2w+1)
#define AST 68

// W3 split, precomputed: per output-col n, 64 words with B-fragment pair
// interleave: word (ks*8 + q*2 + j) = bf16x2 of k = (16ks + 2q + 8j, +1)
__device__ u32 g_bhi[256 * 68];
__device__ u32 g_blo[256 * 68];

__global__ void w3split_kernel(const float* __restrict__ w3) {
    const int n = blockIdx.x;
    const int ws = threadIdx.x;            // 0..63
    const int ks = ws >> 3, rem = ws & 7, q = rem >> 1, j = rem & 1;
    const int k0 = 16 * ks + 2 * q + 8 * j;
    const float v0 = w3[(size_t)k0 * 256 + n];
    const float v1 = w3[(size_t)(k0 + 1) * 256 + n];
    u32 hi, lo; split2(v0, v1, hi, lo);
    g_bhi[n * 68 + ws] = hi;
    g_blo[n * 68 + ws] = lo;
}

// ---------------------------------------------------------------------------
// Point branch: block = one object, 128 threads.
//  Layers 1-2: FFMA/f32x2 (R4 structure), h2 -> shared as bf16 hi/lo split.
//  Layer 3:    mma.sync bf16, 3 split products, fp32 acc; two 64-point halves;
//              4 col-passes of 64; warp w owns cols [w*16, w*16+16) per pass.
//  Max-pool folded into registers + feat_s; pt_out epilogue.
// ---------------------------------------------------------------------------
__global__ __launch_bounds__(128) void point_branch_kernel(
    const float* __restrict__ pts,
    const float* __restrict__ w1, const float* __restrict__ b1,
    const float* __restrict__ w2, const float* __restrict__ b2,
    const float* __restrict__ b3,
    const float* __restrict__ oew, const float* __restrict__ oeb,
    float* __restrict__ out)
{
    __shared__ u32  a_hi_s[64 * AST];   // 17408 B
    __shared__ u32  a_lo_s[64 * AST];   // 17408 B
    __shared__ float h1s[2200];         //  8800 B
    __shared__ float feat_s[256];       //  1024 B

    const int n    = blockIdx.x;
    const int t    = threadIdx.x;
    const int w_   = t >> 5;
    const int lane = t & 31;
    const int mg   = lane >> 2;       // L2: 8 groups of 4? (no: L2 keeps R4 map below)
    const int l2mg = lane >> 3;       // L2: 4 groups of 8 pts
    const int l2ng = lane & 7;        // L2: 8 x 4 cols
    const int c2   = w_ * 32 + l2ng * 4;
    (void)mg;

    const ulonglong2 b2v = __ldg((const ulonglong2*)(b2 + c2));

#pragma unroll 1
    for (int hf = 0; hf < 2; ++hf) {
        // ================= layers 1-2 for this half (2 pg of 32 points) =====
#pragma unroll 1
        for (int pg2 = 0; pg2 < 2; ++pg2) {
            const int pg = hf * 2 + pg2;
            __syncthreads();
            {   // layer 1
                const int pl = t & 31;
                const int j0 = (t >> 5) * 16;
                const size_t pb = ((size_t)n * PPT + (size_t)pg * 32 + pl) * 3;
                const float x = pts[pb + 0], y = pts[pb + 1], z = pts[pb + 2];
                const int hb = H1I(pl);
#pragma unroll
                for (int j = 0; j < 16; j += 4) {
                    const int jj = j0 + j;
                    float4 v;
                    v.x = fmaf(x, __ldg(w1 + jj + 0), fmaf(y, __ldg(w1 + 64 + jj + 0), fmaf(z, __ldg(w1 + 128 + jj + 0), __ldg(b1 + jj + 0))));
                    v.y = fmaf(x, __ldg(w1 + jj + 1), fmaf(y, __ldg(w1 + 64 + jj + 1), fmaf(z, __ldg(w1 + 128 + jj + 1), __ldg(b1 + jj + 1))));
                    v.z = fmaf(x, __ldg(w1 + jj + 2), fmaf(y, __ldg(w1 + 64 + jj + 2), fmaf(z, __ldg(w1 + 128 + jj + 2), __ldg(b1 + jj + 2))));
                    v.w = fmaf(x, __ldg(w1 + jj + 3), fmaf(y, __ldg(w1 + 64 + jj + 3), fmaf(z, __ldg(w1 + 128 + jj + 3), __ldg(b1 + jj + 3))));
                    v.x = fmaxf(v.x, 0.0f); v.y = fmaxf(v.y, 0.0f);
                    v.z = fmaxf(v.z, 0.0f); v.w = fmaxf(v.w, 0.0f);
                    *(float4*)&h1s[hb + jj] = v;
                }
            }
            __syncthreads();

            {   // layer 2: tile 8 pts x 4 cols, f32x2; epilogue: bf16 split store
                u64 acc[8][2];
#pragma unroll
                for (int i = 0; i < 8; ++i) { acc[i][0] = b2v.x; acc[i][1] = b2v.y; }
#pragma unroll 1
                for (int k = 0; k < 64; k += 4) {
                    float4 a[8];
#pragma unroll
                    for (int i = 0; i < 8; ++i)
                        a[i] = *(const float4*)&h1s[H1I(l2mg * 8 + i) + k];
                    ulonglong2 wv[4];
#pragma unroll
                    for (int q = 0; q < 4; ++q)
                        wv[q] = __ldg((const ulonglong2*)(w2 + (size_t)(k + q) * 128 + c2));
#pragma unroll
                    for (int i = 0; i < 8; ++i) {
                        const u64 s0 = pk2(a[i].x, a[i].x);
                        fma2(acc[i][0], s0, wv[0].x); fma2(acc[i][1], s0, wv[0].y);
                        const u64 s1 = pk2(a[i].y, a[i].y);
                        fma2(acc[i][0], s1, wv[1].x); fma2(acc[i][1], s1, wv[1].y);
                        const u64 s2 = pk2(a[i].z, a[i].z);
                        fma2(acc[i][0], s2, wv[2].x); fma2(acc[i][1], s2, wv[2].y);
                        const u64 s3 = pk2(a[i].w, a[i].w);
                        fma2(acc[i][0], s3, wv[3].x); fma2(acc[i][1], s3, wv[3].y);
                    }
                }
#pragma unroll
                for (int i = 0; i < 8; ++i) {
                    const int rl = pg2 * 32 + l2mg * 8 + i;   // row within half
                    const int wd = c2 >> 1;
                    const float2 p0 = up2(acc[i][0]), p1 = up2(acc[i][1]);
                    const float f0 = fmaxf(p0.x, 0.0f), f1 = fmaxf(p0.y, 0.0f);
                    const float f2 = fmaxf(p1.x, 0.0f), f3 = fmaxf(p1.y, 0.0f);
                    u32 hi0, lo0, hi1, lo1;
                    split2(f0, f1, hi0, lo0);
                    split2(f2, f3, hi1, lo1);
                    a_hi_s[rl * AST + wd]     = hi0;
                    a_hi_s[rl * AST + wd + 1] = hi1;
                    a_lo_s[rl * AST + wd]     = lo0;
                    a_lo_s[rl * AST + wd + 1] = lo1;
                }
            }
        }
        __syncthreads();   // a_hi/a_lo complete for this half

        // ================= layer 3: mma.sync over this half ==================
#pragma unroll 1
        for (int np = 0; np < 4; ++np) {
            // B fragments register-resident: warp owns 16 cols = 2 n-tiles
            uint2 bh[2][8], bl[2][8];
#pragma unroll
            for (int nt = 0; nt < 2; ++nt) {
                const int gcol = np * 64 + w_ * 16 + nt * 8 + (lane >> 2);
                const u32 base = gcol * 68 + (lane & 3) * 2;
#pragma unroll
                for (int ks = 0; ks < 8; ++ks) {
                    bh[nt][ks] = __ldg((const uint2*)(g_bhi + base + ks * 8));
                    bl[nt][ks] = __ldg((const uint2*)(g_blo + base + ks * 8));
                }
            }

            float rm[2][2] = { {-3.0e38f, -3.0e38f}, {-3.0e38f, -3.0e38f} };

#pragma unroll
            for (int mt = 0; mt < 4; ++mt) {
                float acc[2][4];
#pragma unroll
                for (int nt = 0; nt < 2; ++nt)
#pragma unroll
                    for (int q = 0; q < 4; ++q) acc[nt][q] = 0.0f;

#pragma unroll
                for (int ks = 0; ks < 8; ++ks) {
                    const int r0 = mt * 16 + (lane >> 2);
                    const int w0 = ks * 8 + (lane & 3);
                    const u32 ah0 = a_hi_s[r0 * AST + w0];
                    const u32 ah1 = a_hi_s[(r0 + 8) * AST + w0];
                    const u32 ah2 = a_hi_s[r0 * AST + w0 + 4];
                    const u32 ah3 = a_hi_s[(r0 + 8) * AST + w0 + 4];
                    const u32 al0 = a_lo_s[r0 * AST + w0];
                    const u32 al1 = a_lo_s[(r0 + 8) * AST + w0];
                    const u32 al2 = a_lo_s[r0 * AST + w0 + 4];
                    const u32 al3 = a_lo_s[(r0 + 8) * AST + w0 + 4];
#pragma unroll
                    for (int nt = 0; nt < 2; ++nt) {
                        mma_bf16(acc[nt], ah0, ah1, ah2, ah3, bh[nt][ks].x, bh[nt][ks].y);
                        mma_bf16(acc[nt], ah0, ah1, ah2, ah3, bl[nt][ks].x, bl[nt][ks].y);
                        mma_bf16(acc[nt], al0, al1, al2, al3, bh[nt][ks].x, bh[nt][ks].y);
                    }
                }
#pragma unroll
                for (int nt = 0; nt < 2; ++nt) {
                    rm[nt][0] = fmaxf(rm[nt][0], fmaxf(acc[nt][0], acc[nt][2]));
                    rm[nt][1] = fmaxf(rm[nt][1], fmaxf(acc[nt][1], acc[nt][3]));
                }
            }

            // reduce over rows held by lanes sharing (lane&3); lanes<4 write
#pragma unroll
            for (int nt = 0; nt < 2; ++nt) {
#pragma unroll
                for (int j = 0; j < 2; ++j) {
                    float m = rm[nt][j];
                    m = fmaxf(m, __shfl_xor_sync(0xffffffffu, m, 4));
                    m = fmaxf(m, __shfl_xor_sync(0xffffffffu, m, 8));
                    m = fmaxf(m, __shfl_xor_sync(0xffffffffu, m, 16));
                    if (lane < 4) {
                        const int col = np * 64 + w_ * 16 + nt * 8 + 2 * lane + j;
                        if (hf == 0) feat_s[col] = m;
                        else         feat_s[col] = fmaxf(feat_s[col], m) + __ldg(b3 + col);
                    }
                }
            }
        }
    }
    __syncthreads();

    // ---- pt_out = feat @ oe_w + oe_b
    if (t < EMB) {
        float acc = __ldg(oeb + t);
#pragma unroll 4
        for (int k = 0; k < 256; k += 4) {
            const float4 f = *(const float4*)&feat_s[k];
            acc = fmaf(f.x, __ldg(oew + (size_t)(k + 0) * EMB + t), acc);
            acc = fmaf(f.y, __ldg(oew + (size_t)(k + 1) * EMB + t), acc);
            acc = fmaf(f.z, __ldg(oew + (size_t)(k + 2) * EMB + t), acc);
            acc = fmaf(f.w, __ldg(oew + (size_t)(k + 3) * EMB + t), acc);
        }
        out[(size_t)n * OUTW + EMB + t] = acc;
    }
}

// ---------------------------------------------------------------------------
// Node branch (unchanged)
// ---------------------------------------------------------------------------
__global__ __launch_bounds__(256) void node_branch_kernel(
    const float* __restrict__ srcf,
    const float* __restrict__ reff,
    const void*  __restrict__ counts_raw,
    const float* __restrict__ w1, const float* __restrict__ b1,
    const float* __restrict__ w2, const float* __restrict__ b2,
    const float* __restrict__ sew, const float* __restrict__ seb,
    float* __restrict__ out)
{
    __shared__ float xs[8 * 260];
    __shared__ float hs[8 * 260];
    __shared__ int srow[8];
    __shared__ int sflag[8];

    const int t = threadIdx.x;
    const long long o0 = (long long)blockIdx.x * 8;

    if (t < 8) {
        const int* c32 = (const int*)counts_raw;
        const bool is64 = (c32[1] == 0 && c32[3] == 0);
        const long long o = o0 + t;
        long long cum = 0, ssum = 0, rsum = 0, idx = 0;
        int flag = 0;
        for (int b = 0; b < NB; ++b) {
            long long sc, rc;
            if (is64) { sc = ((const long long*)counts_raw)[2 * b]; rc = ((const long long*)counts_raw)[2 * b + 1]; }
            else      { sc = c32[2 * b]; rc = c32[2 * b + 1]; }
            const long long tot = sc + rc;
            if (o < cum + tot) {
                const long long off = o - cum;
                if (off < sc) { flag = 0; idx = ssum + off; }
                else          { flag = 1; idx = rsum + (off - sc); }
                break;
            }
            cum += tot; ssum += sc; rsum += rc;
        }
        srow[t] = (int)idx; sflag[t] = flag;
    }
    __syncthreads();

#pragma unroll
    for (int r = 0; r < 8; ++r) {
        const float* base = sflag[r] ? reff : srcf;
        xs[r * 260 + t] = base[(size_t)srow[r] * FEAT + t];
    }
    __syncthreads();

    float acc[8];
    {
        const float bv = __ldg(b1 + t);
#pragma unroll
        for (int r = 0; r < 8; ++r) acc[r] = bv;
#pragma unroll 1
        for (int k = 0; k < 256; k += 4) {
            const float w0 = __ldg(w1 + (size_t)(k + 0) * 256 + t);
            const float wq1 = __ldg(w1 + (size_t)(k + 1) * 256 + t);
            const float wq2 = __ldg(w1 + (size_t)(k + 2) * 256 + t);
            const float wq3 = __ldg(w1 + (size_t)(k + 3) * 256 + t);
#pragma unroll
            for (int r = 0; r < 8; ++r) {
                float4 xv = *(const float4*)&xs[r * 260 + k];
                acc[r] = fmaf(xv.x, w0, acc[r]);
                acc[r] = fmaf(xv.y, wq1, acc[r]);
                acc[r] = fmaf(xv.z, wq2, acc[r]);
                acc[r] = fmaf(xv.w, wq3, acc[r]);
            }
        }
#pragma unroll
        for (int r = 0; r < 8; ++r) hs[r * 260 + t] = fmaxf(acc[r], 0.0f);
    }
    __syncthreads();
    {
        const float bv = __ldg(b2 + t);
#pragma unroll
        for (int r = 0; r < 8; ++r) acc[r] = bv;
#pragma unroll 1
        for (int k = 0; k < 256; k += 4) {
            const float w0 = __ldg(w2 + (size_t)(k + 0) * 256 + t);
            const float wq1 = __ldg(w2 + (size_t)(k + 1) * 256 + t);
            const float wq2 = __ldg(w2 + (size_t)(k + 2) * 256 + t);
            const float wq3 = __ldg(w2 + (size_t)(k + 3) * 256 + t);
#pragma unroll
            for (int r = 0; r < 8; ++r) {
                float4 xv = *(const float4*)&hs[r * 260 + k];
                acc[r] = fmaf(xv.x, w0, acc[r]);
                acc[r] = fmaf(xv.y, wq1, acc[r]);
                acc[r] = fmaf(xv.z, wq2, acc[r]);
                acc[r] = fmaf(xv.w, wq3, acc[r]);
            }
        }
#pragma unroll
        for (int r = 0; r < 8; ++r) xs[r * 260 + t] = acc[r];
    }
    __syncthreads();

    if (t < EMB) {
        float accs[8];
        const float bv = __ldg(seb + t);
#pragma unroll
        for (int r = 0; r < 8; ++r) accs[r] = bv;
#pragma unroll 1
        for (int k = 0; k < 256; k += 4) {
            const float w0 = __ldg(sew + (size_t)(k + 0) * EMB + t);
            const float wq1 = __ldg(sew + (size_t)(k + 1) * EMB + t);
            const float wq2 = __ldg(sew + (size_t)(k + 2) * EMB + t);
            const float wq3 = __ldg(sew + (size_t)(k + 3) * EMB + t);
#pragma unroll
            for (int r = 0; r < 8; ++r) {
                float4 ev = *(const float4*)&xs[r * 260 + k];
                accs[r] = fmaf(ev.x, w0, accs[r]);
                accs[r] = fmaf(ev.y, wq1, accs[r]);
                accs[r] = fmaf(ev.z, wq2, accs[r]);
                accs[r] = fmaf(ev.w, wq3, accs[r]);
            }
        }
#pragma unroll
        for (int r = 0; r < 8; ++r)
            out[(size_t)(o0 + r) * OUTW + t] = accs[r];
    }
}

extern "C" void kernel_launch(void* const* d_in, const int* in_sizes, int n_in,
                              void* d_out, int out_size)
{
    const float* pts    = (const float*)d_in[0];
    const float* srcf   = (const float*)d_in[1];
    const float* reff   = (const float*)d_in[2];
    const void*  counts = d_in[3];
    const float* sg_w1  = (const float*)d_in[6];
    const float* sg_b1  = (const float*)d_in[7];
    const float* sg_w2  = (const float*)d_in[8];
    const float* sg_b2  = (const float*)d_in[9];
    const float* se_w   = (const float*)d_in[10];
    const float* se_b   = (const float*)d_in[11];
    const float* p_w1   = (const float*)d_in[12];
    const float* p_b1   = (const float*)d_in[13];
    const float* p_w2   = (const float*)d_in[14];
    const float* p_b2   = (const float*)d_in[15];
    const float* p_w3   = (const float*)d_in[16];
    const float* p_b3   = (const float*)d_in[17];
    const float* oe_w   = (const float*)d_in[18];
    const float* oe_b   = (const float*)d_in[19];
    float* out = (float*)d_out;

    w3split_kernel<<<256, 64>>>(p_w3);
    node_branch_kernel<<<N_TOT / 8, 256>>>(srcf, reff, counts,
                                           sg_w1, sg_b1, sg_w2, sg_b2,
                                           se_w, se_b, out);
    point_branch_kernel<<<N_TOT, 128>>>(pts, p_w1, p_b1, p_w2, p_b2,
                                        p_b3, oe_w, oe_b, out);
}

// round 8
// speedup vs baseline: 2.7405x; 1.2843x over previous
#include <cuda_runtime.h>
#include <cuda_bf16.h>
#include <stdint.h>

#define NB    16
#define N_TOT 16384
#define PPT   128
#define FEAT  256
#define EMB   100
#define OUTW  200

typedef unsigned long long u64;
typedef unsigned int u32;

// ---------------- bf16 split helper ----------------
__device__ __forceinline__ void split2(float x0, float x1, u32& hi, u32& lo) {
    __nv_bfloat16 h0 = __float2bfloat16(x0);
    __nv_bfloat16 h1 = __float2bfloat16(x1);
    __nv_bfloat16 l0 = __float2bfloat16(x0 - __bfloat162float(h0));
    __nv_bfloat16 l1 = __float2bfloat16(x1 - __bfloat162float(h1));
    __nv_bfloat162 hh = __halves2bfloat162(h0, h1);
    __nv_bfloat162 ll = __halves2bfloat162(l0, l1);
    hi = *(u32*)&hh; lo = *(u32*)&ll;
}

// ---------------- mma / ldmatrix (portable ISA) ----------------
__device__ __forceinline__ void mma_bf16(float* c,
                                         u32 a0, u32 a1, u32 a2, u32 a3,
                                         u32 b0, u32 b1) {
    asm("mma.sync.aligned.m16n8k16.row.col.f32.bf16.bf16.f32 "
        "{%0,%1,%2,%3}, {%4,%5,%6,%7}, {%8,%9}, {%0,%1,%2,%3};"
        : "+f"(c[0]), "+f"(c[1]), "+f"(c[2]), "+f"(c[3])
        : "r"(a0), "r"(a1), "r"(a2), "r"(a3), "r"(b0), "r"(b1));
}
__device__ __forceinline__ void ldsm_x4(u32& r0, u32& r1, u32& r2, u32& r3, u32 saddr) {
    asm volatile("ldmatrix.sync.aligned.m8n8.x4.shared.b16 {%0,%1,%2,%3}, [%4];"
                 : "=r"(r0), "=r"(r1), "=r"(r2), "=r"(r3) : "r"(saddr));
}
__device__ __forceinline__ u32 smem_u32(const void* p) {
    u32 a; asm("{ .reg .u64 t; cvta.to.shared.u64 t, %1; cvt.u32.u64 %0, t; }" : "=r"(a) : "l"(p));
    return a;
}

// Strides (u32 words). Both ≡ 4 mod 32 banks -> conflict-free ldmatrix phases.
#define H1ST 36   // h1: 32 data words + 4 pad
#define H2ST 68   // h2: 64 data words + 4 pad

// Precomputed weight splits (B fragments, k-major per col).
// Word (ks*8 + q*2 + j) = bf16x2 of k = (16ks + 2q + 8j, +1).
__device__ u32 g_bhi[256 * 68];   // W3 (K=128 -> 64 words/col, stride 68)
__device__ u32 g_blo[256 * 68];
__device__ u32 g_w2h[128 * 32];   // W2 (K=64 -> 32 words/col)
__device__ u32 g_w2l[128 * 32];

__global__ void w3split_kernel(const float* __restrict__ w3) {
    const int n = blockIdx.x;
    const int ws = threadIdx.x;            // 0..63
    const int ks = ws >> 3, rem = ws & 7, q = rem >> 1, j = rem & 1;
    const int k0 = 16 * ks + 2 * q + 8 * j;
    u32 hi, lo;
    split2(w3[(size_t)k0 * 256 + n], w3[(size_t)(k0 + 1) * 256 + n], hi, lo);
    g_bhi[n * 68 + ws] = hi;
    g_blo[n * 68 + ws] = lo;
}
__global__ void w2split_kernel(const float* __restrict__ w2) {
    const int n = blockIdx.x;
    const int ws = threadIdx.x;            // 0..31
    const int ks = ws >> 3, rem = ws & 7, q = rem >> 1, j = rem & 1;
    const int k0 = 16 * ks + 2 * q + 8 * j;
    u32 hi, lo;
    split2(w2[(size_t)k0 * 128 + n], w2[(size_t)(k0 + 1) * 128 + n], hi, lo);
    g_w2h[n * 32 + ws] = hi;
    g_w2l[n * 32 + ws] = lo;
}

// Dynamic smem: h2h(4352) h2l(4352) h1h(2304) h1l(2304) = 13312 words = 53248 B
#define DSM_WORDS 13312
#define DSM_BYTES (DSM_WORDS * 4)

// ---------------------------------------------------------------------------
// Point branch: block = one object, 128 threads, two 64-point halves.
//  L1: FFMA -> h1 bf16 hi/lo split in shared.
//  L2: mma.sync (3 split products) -> relu -> h2 bf16 hi/lo split in shared.
//  L3: mma.sync (3 split products), A via ldmatrix, B from gmem regs;
//      max-pool in registers -> feat_s. pt_out epilogue.
// ---------------------------------------------------------------------------
__global__ __launch_bounds__(128) void point_branch_kernel(
    const float* __restrict__ pts,
    const float* __restrict__ w1, const float* __restrict__ b1,
    const float* __restrict__ b2, const float* __restrict__ b3,
    const float* __restrict__ oew, const float* __restrict__ oeb,
    float* __restrict__ out)
{
    extern __shared__ u32 dsm[];
    u32* h2h = dsm;
    u32* h2l = dsm + 4352;
    u32* h1h = dsm + 8704;
    u32* h1l = dsm + 11008;
    __shared__ float feat_s[256];

    const u32 h2h_u = smem_u32(h2h), h2l_u = smem_u32(h2l);
    const u32 h1h_u = smem_u32(h1h), h1l_u = smem_u32(h1l);

    const int n    = blockIdx.x;
    const int t    = threadIdx.x;
    const int w_   = t >> 5;
    const int lane = t & 31;

    // ldmatrix lane address components (row = base + (lane&15), +4 words if lane>=16)
    const int lm_row = lane & 15;
    const int lm_col = (lane >> 4) << 2;

#pragma unroll 1
    for (int hf = 0; hf < 2; ++hf) {
        __syncthreads();   // h1/h2 free (prior half's L2/L3 done)

        // ================= layer 1: 64 points -> h1 split ====================
#pragma unroll
        for (int pg2 = 0; pg2 < 2; ++pg2) {
            const int pl = t & 31;               // point in group
            const int j0 = (t >> 5) * 16;        // col base
            const int row = pg2 * 32 + pl;       // row within half
            const size_t pb = ((size_t)n * PPT + (size_t)(hf * 2 + pg2) * 32 + pl) * 3;
            const float x = pts[pb + 0], y = pts[pb + 1], z = pts[pb + 2];
            float v[16];
#pragma unroll
            for (int j = 0; j < 16; ++j) {
                const int jj = j0 + j;
                float r = fmaf(x, __ldg(w1 + jj), fmaf(y, __ldg(w1 + 64 + jj), fmaf(z, __ldg(w1 + 128 + jj), __ldg(b1 + jj))));
                v[j] = fmaxf(r, 0.0f);
            }
            u32 hw[8], lw[8];
#pragma unroll
            for (int q = 0; q < 8; ++q) split2(v[2 * q], v[2 * q + 1], hw[q], lw[q]);
            const int wb = row * H1ST + (j0 >> 1);
            *(uint4*)&h1h[wb]     = make_uint4(hw[0], hw[1], hw[2], hw[3]);
            *(uint4*)&h1h[wb + 4] = make_uint4(hw[4], hw[5], hw[6], hw[7]);
            *(uint4*)&h1l[wb]     = make_uint4(lw[0], lw[1], lw[2], lw[3]);
            *(uint4*)&h1l[wb + 4] = make_uint4(lw[4], lw[5], lw[6], lw[7]);
        }
        __syncthreads();

        // ================= layer 2: mma, warp owns cols w_*32..+32 ==========
#pragma unroll 1
        for (int nt = 0; nt < 4; ++nt) {
            const int gcol = w_ * 32 + nt * 8 + (lane >> 2);
            const u32 bbase = gcol * 32 + (lane & 3) * 2;
            uint2 bh[4], bl[4];
#pragma unroll
            for (int ks = 0; ks < 4; ++ks) {
                bh[ks] = __ldg((const uint2*)(g_w2h + bbase + ks * 8));
                bl[ks] = __ldg((const uint2*)(g_w2l + bbase + ks * 8));
            }
            const float2 bb = __ldg((const float2*)(b2 + w_ * 32 + nt * 8 + 2 * (lane & 3)));

#pragma unroll
            for (int mt = 0; mt < 4; ++mt) {
                float acc[4] = { bb.x, bb.y, bb.x, bb.y };
#pragma unroll
                for (int ks = 0; ks < 4; ++ks) {
                    const u32 aoff = (u32)(((mt * 16 + lm_row) * H1ST + ks * 8 + lm_col) * 4);
                    u32 ah0, ah1, ah2, ah3, al0, al1, al2, al3;
                    ldsm_x4(ah0, ah1, ah2, ah3, h1h_u + aoff);
                    ldsm_x4(al0, al1, al2, al3, h1l_u + aoff);
                    mma_bf16(acc, ah0, ah1, ah2, ah3, bh[ks].x, bh[ks].y);
                    mma_bf16(acc, ah0, ah1, ah2, ah3, bl[ks].x, bl[ks].y);
                    mma_bf16(acc, al0, al1, al2, al3, bh[ks].x, bh[ks].y);
                }
                // relu + split + store h2 (rows mt*16+(lane>>2), +8)
                const int r0 = mt * 16 + (lane >> 2);
                const int wd = w_ * 16 + nt * 4 + (lane & 3);
                u32 hi, lo;
                split2(fmaxf(acc[0], 0.0f), fmaxf(acc[1], 0.0f), hi, lo);
                h2h[r0 * H2ST + wd] = hi; h2l[r0 * H2ST + wd] = lo;
                split2(fmaxf(acc[2], 0.0f), fmaxf(acc[3], 0.0f), hi, lo);
                h2h[(r0 + 8) * H2ST + wd] = hi; h2l[(r0 + 8) * H2ST + wd] = lo;
            }
        }
        __syncthreads();   // h2 split complete

        // ================= layer 3: mma over this half ======================
#pragma unroll 1
        for (int np = 0; np < 4; ++np) {
            uint2 bh[2][8], bl[2][8];
#pragma unroll
            for (int nt = 0; nt < 2; ++nt) {
                const int gcol = np * 64 + w_ * 16 + nt * 8 + (lane >> 2);
                const u32 base = gcol * 68 + (lane & 3) * 2;
#pragma unroll
                for (int ks = 0; ks < 8; ++ks) {
                    bh[nt][ks] = __ldg((const uint2*)(g_bhi + base + ks * 8));
                    bl[nt][ks] = __ldg((const uint2*)(g_blo + base + ks * 8));
                }
            }

            float rm[2][2] = { {-3.0e38f, -3.0e38f}, {-3.0e38f, -3.0e38f} };

#pragma unroll
            for (int mt = 0; mt < 4; ++mt) {
                float acc[2][4];
#pragma unroll
                for (int nt = 0; nt < 2; ++nt)
#pragma unroll
                    for (int q = 0; q < 4; ++q) acc[nt][q] = 0.0f;

#pragma unroll
                for (int ks = 0; ks < 8; ++ks) {
                    const u32 aoff = (u32)(((mt * 16 + lm_row) * H2ST + ks * 8 + lm_col) * 4);
                    u32 ah0, ah1, ah2, ah3, al0, al1, al2, al3;
                    ldsm_x4(ah0, ah1, ah2, ah3, h2h_u + aoff);
                    ldsm_x4(al0, al1, al2, al3, h2l_u + aoff);
#pragma unroll
                    for (int nt = 0; nt < 2; ++nt) {
                        mma_bf16(acc[nt], ah0, ah1, ah2, ah3, bh[nt][ks].x, bh[nt][ks].y);
                        mma_bf16(acc[nt], ah0, ah1, ah2, ah3, bl[nt][ks].x, bl[nt][ks].y);
                        mma_bf16(acc[nt], al0, al1, al2, al3, bh[nt][ks].x, bh[nt][ks].y);
                    }
                }
#pragma unroll
                for (int nt = 0; nt < 2; ++nt) {
                    rm[nt][0] = fmaxf(rm[nt][0], fmaxf(acc[nt][0], acc[nt][2]));
                    rm[nt][1] = fmaxf(rm[nt][1], fmaxf(acc[nt][1], acc[nt][3]));
                }
            }

#pragma unroll
            for (int nt = 0; nt < 2; ++nt) {
#pragma unroll
                for (int j = 0; j < 2; ++j) {
                    float m = rm[nt][j];
                    m = fmaxf(m, __shfl_xor_sync(0xffffffffu, m, 4));
                    m = fmaxf(m, __shfl_xor_sync(0xffffffffu, m, 8));
                    m = fmaxf(m, __shfl_xor_sync(0xffffffffu, m, 16));
                    if (lane < 4) {
                        const int col = np * 64 + w_ * 16 + nt * 8 + 2 * lane + j;
                        if (hf == 0) feat_s[col] = m;
                        else         feat_s[col] = fmaxf(feat_s[col], m) + __ldg(b3 + col);
                    }
                }
            }
        }
    }
    __syncthreads();

    // ---- pt_out = feat @ oe_w + oe_b
    if (t < EMB) {
        float acc = __ldg(oeb + t);
#pragma unroll 4
        for (int k = 0; k < 256; k += 4) {
            const float4 f = *(const float4*)&feat_s[k];
            acc = fmaf(f.x, __ldg(oew + (size_t)(k + 0) * EMB + t), acc);
            acc = fmaf(f.y, __ldg(oew + (size_t)(k + 1) * EMB + t), acc);
            acc = fmaf(f.z, __ldg(oew + (size_t)(k + 2) * EMB + t), acc);
            acc = fmaf(f.w, __ldg(oew + (size_t)(k + 3) * EMB + t), acc);
        }
        out[(size_t)n * OUTW + EMB + t] = acc;
    }
}

// ---------------------------------------------------------------------------
// Node branch (unchanged)
// ---------------------------------------------------------------------------
__global__ __launch_bounds__(256) void node_branch_kernel(
    const float* __restrict__ srcf,
    const float* __restrict__ reff,
    const void*  __restrict__ counts_raw,
    const float* __restrict__ w1, const float* __restrict__ b1,
    const float* __restrict__ w2, const float* __restrict__ b2,
    const float* __restrict__ sew, const float* __restrict__ seb,
    float* __restrict__ out)
{
    __shared__ float xs[8 * 260];
    __shared__ float hs[8 * 260];
    __shared__ int srow[8];
    __shared__ int sflag[8];

    const int t = threadIdx.x;
    const long long o0 = (long long)blockIdx.x * 8;

    if (t < 8) {
        const int* c32 = (const int*)counts_raw;
        const bool is64 = (c32[1] == 0 && c32[3] == 0);
        const long long o = o0 + t;
        long long cum = 0, ssum = 0, rsum = 0, idx = 0;
        int flag = 0;
        for (int b = 0; b < NB; ++b) {
            long long sc, rc;
            if (is64) { sc = ((const long long*)counts_raw)[2 * b]; rc = ((const long long*)counts_raw)[2 * b + 1]; }
            else      { sc = c32[2 * b]; rc = c32[2 * b + 1]; }
            const long long tot = sc + rc;
            if (o < cum + tot) {
                const long long off = o - cum;
                if (off < sc) { flag = 0; idx = ssum + off; }
                else          { flag = 1; idx = rsum + (off - sc); }
                break;
            }
            cum += tot; ssum += sc; rsum += rc;
        }
        srow[t] = (int)idx; sflag[t] = flag;
    }
    __syncthreads();

#pragma unroll
    for (int r = 0; r < 8; ++r) {
        const float* base = sflag[r] ? reff : srcf;
        xs[r * 260 + t] = base[(size_t)srow[r] * FEAT + t];
    }
    __syncthreads();

    float acc[8];
    {
        const float bv = __ldg(b1 + t);
#pragma unroll
        for (int r = 0; r < 8; ++r) acc[r] = bv;
#pragma unroll 1
        for (int k = 0; k < 256; k += 4) {
            const float w0 = __ldg(w1 + (size_t)(k + 0) * 256 + t);
            const float wq1 = __ldg(w1 + (size_t)(k + 1) * 256 + t);
            const float wq2 = __ldg(w1 + (size_t)(k + 2) * 256 + t);
            const float wq3 = __ldg(w1 + (size_t)(k + 3) * 256 + t);
#pragma unroll
            for (int r = 0; r < 8; ++r) {
                float4 xv = *(const float4*)&xs[r * 260 + k];
                acc[r] = fmaf(xv.x, w0, acc[r]);
                acc[r] = fmaf(xv.y, wq1, acc[r]);
                acc[r] = fmaf(xv.z, wq2, acc[r]);
                acc[r] = fmaf(xv.w, wq3, acc[r]);
            }
        }
#pragma unroll
        for (int r = 0; r < 8; ++r) hs[r * 260 + t] = fmaxf(acc[r], 0.0f);
    }
    __syncthreads();
    {
        const float bv = __ldg(b2 + t);
#pragma unroll
        for (int r = 0; r < 8; ++r) acc[r] = bv;
#pragma unroll 1
        for (int k = 0; k < 256; k += 4) {
            const float w0 = __ldg(w2 + (size_t)(k + 0) * 256 + t);
            const float wq1 = __ldg(w2 + (size_t)(k + 1) * 256 + t);
            const float wq2 = __ldg(w2 + (size_t)(k + 2) * 256 + t);
            const float wq3 = __ldg(w2 + (size_t)(k + 3) * 256 + t);
#pragma unroll
            for (int r = 0; r < 8; ++r) {
                float4 xv = *(const float4*)&hs[r * 260 + k];
                acc[r] = fmaf(xv.x, w0, acc[r]);
                acc[r] = fmaf(xv.y, wq1, acc[r]);
                acc[r] = fmaf(xv.z, wq2, acc[r]);
                acc[r] = fmaf(xv.w, wq3, acc[r]);
            }
        }
#pragma unroll
        for (int r = 0; r < 8; ++r) xs[r * 260 + t] = acc[r];
    }
    __syncthreads();

    if (t < EMB) {
        float accs[8];
        const float bv = __ldg(seb + t);
#pragma unroll
        for (int r = 0; r < 8; ++r) accs[r] = bv;
#pragma unroll 1
        for (int k = 0; k < 256; k += 4) {
            const float w0 = __ldg(sew + (size_t)(k + 0) * EMB + t);
            const float wq1 = __ldg(sew + (size_t)(k + 1) * EMB + t);
            const float wq2 = __ldg(sew + (size_t)(k + 2) * EMB + t);
            const float wq3 = __ldg(sew + (size_t)(k + 3) * EMB + t);
#pragma unroll
            for (int r = 0; r < 8; ++r) {
                float4 ev = *(const float4*)&xs[r * 260 + k];
                accs[r] = fmaf(ev.x, w0, accs[r]);
                accs[r] = fmaf(ev.y, wq1, accs[r]);
                accs[r] = fmaf(ev.z, wq2, accs[r]);
                accs[r] = fmaf(ev.w, wq3, accs[r]);
            }
        }
#pragma unroll
        for (int r = 0; r < 8; ++r)
            out[(size_t)(o0 + r) * OUTW + t] = accs[r];
    }
}

extern "C" void kernel_launch(void* const* d_in, const int* in_sizes, int n_in,
                              void* d_out, int out_size)
{
    const float* pts    = (const float*)d_in[0];
    const float* srcf   = (const float*)d_in[1];
    const float* reff   = (const float*)d_in[2];
    const void*  counts = d_in[3];
    const float* sg_w1  = (const float*)d_in[6];
    const float* sg_b1  = (const float*)d_in[7];
    const float* sg_w2  = (const float*)d_in[8];
    const float* sg_b2  = (const float*)d_in[9];
    const float* se_w   = (const float*)d_in[10];
    const float* se_b   = (const float*)d_in[11];
    const float* p_w1   = (const float*)d_in[12];
    const float* p_b1   = (const float*)d_in[13];
    const float* p_w2   = (const float*)d_in[14];
    const float* p_b2   = (const float*)d_in[15];
    const float* p_w3   = (const float*)d_in[16];
    const float* p_b3   = (const float*)d_in[17];
    const float* oe_w   = (const float*)d_in[18];
    const float* oe_b   = (const float*)d_in[19];
    float* out = (float*)d_out;

    cudaFuncSetAttribute(point_branch_kernel,
                         cudaFuncAttributeMaxDynamicSharedMemorySize, DSM_BYTES);

    w3split_kernel<<<256, 64>>>(p_w3);
    w2split_kernel<<<128, 32>>>(p_w2);
    node_branch_kernel<<<N_TOT / 8, 256>>>(srcf, reff, counts,
                                           sg_w1, sg_b1, sg_w2, sg_b2,
                                           se_w, se_b, out);
    point_branch_kernel<<<N_TOT, 128, DSM_BYTES>>>(pts, p_w1, p_b1, p_b2, p_b3,
                                                   oe_w, oe_b, out);
}

// round 9
// speedup vs baseline: 3.5713x; 1.3031x over previous
#include <cuda_runtime.h>
#include <cuda_bf16.h>
#include <cuda_fp16.h>
#include <stdint.h>

#define NB    16
#define N_TOT 16384
#define PPT   128
#define FEAT  256
#define EMB   100
#define OUTW  200

typedef unsigned long long u64;
typedef unsigned int u32;

// ---------------- split helpers ----------------
__device__ __forceinline__ void split2_bf(float x0, float x1, u32& hi, u32& lo) {
    __nv_bfloat16 h0 = __float2bfloat16(x0);
    __nv_bfloat16 h1 = __float2bfloat16(x1);
    __nv_bfloat16 l0 = __float2bfloat16(x0 - __bfloat162float(h0));
    __nv_bfloat16 l1 = __float2bfloat16(x1 - __bfloat162float(h1));
    __nv_bfloat162 hh = __halves2bfloat162(h0, h1);
    __nv_bfloat162 ll = __halves2bfloat162(l0, l1);
    hi = *(u32*)&hh; lo = *(u32*)&ll;
}

// ---------------- mma / ldmatrix (portable ISA) ----------------
__device__ __forceinline__ void mma_bf16(float* c,
                                         u32 a0, u32 a1, u32 a2, u32 a3,
                                         u32 b0, u32 b1) {
    asm("mma.sync.aligned.m16n8k16.row.col.f32.bf16.bf16.f32 "
        "{%0,%1,%2,%3}, {%4,%5,%6,%7}, {%8,%9}, {%0,%1,%2,%3};"
        : "+f"(c[0]), "+f"(c[1]), "+f"(c[2]), "+f"(c[3])
        : "r"(a0), "r"(a1), "r"(a2), "r"(a3), "r"(b0), "r"(b1));
}
__device__ __forceinline__ void mma_f16(float* c,
                                        u32 a0, u32 a1, u32 a2, u32 a3,
                                        u32 b0, u32 b1) {
    asm("mma.sync.aligned.m16n8k16.row.col.f32.f16.f16.f32 "
        "{%0,%1,%2,%3}, {%4,%5,%6,%7}, {%8,%9}, {%0,%1,%2,%3};"
        : "+f"(c[0]), "+f"(c[1]), "+f"(c[2]), "+f"(c[3])
        : "r"(a0), "r"(a1), "r"(a2), "r"(a3), "r"(b0), "r"(b1));
}
__device__ __forceinline__ void ldsm_x4(u32& r0, u32& r1, u32& r2, u32& r3, u32 saddr) {
    asm volatile("ldmatrix.sync.aligned.m8n8.x4.shared.b16 {%0,%1,%2,%3}, [%4];"
                 : "=r"(r0), "=r"(r1), "=r"(r2), "=r"(r3) : "r"(saddr));
}
__device__ __forceinline__ u32 smem_u32(const void* p) {
    u32 a; asm("{ .reg .u64 t; cvta.to.shared.u64 t, %1; cvt.u32.u64 %0, t; }" : "=r"(a) : "l"(p));
    return a;
}

#define H1ST 36   // h1 rows: 32 data words + 4 pad (bf16x2)
#define H2ST 68   // h2 rows: 64 data words + 4 pad (fp16x2)

#define LO_SCALE  2048.0f
#define LO_INV    4.8828125e-4f

// Coalesced B-fragment layouts: group L -> 32 lanes x uint2 contiguous.
// W3 (fp16): L = ((np*4 + w)*2 + nt)*8 + ks, 256 groups. lo scaled by 2^11.
__device__ u32 g3h[256 * 64];
__device__ u32 g3l[256 * 64];
// W2 (bf16): L = (w*4 + nt)*4 + ks, 64 groups.
__device__ u32 g2h[64 * 64];
__device__ u32 g2l[64 * 64];

__global__ void w3frag_kernel(const float* __restrict__ w3) {
    const int gid = blockIdx.x * 128 + threadIdx.x;   // 8192 threads
    const int L = gid >> 5, lane = gid & 31;
    const int ks = L & 7, nt = (L >> 3) & 1, w = (L >> 4) & 3, np = L >> 6;
    const int gcol = np * 64 + w * 16 + nt * 8 + (lane >> 2);
    const int k0 = 16 * ks + 2 * (lane & 3);
    const float v00 = w3[(size_t)k0 * 256 + gcol];
    const float v01 = w3[(size_t)(k0 + 1) * 256 + gcol];
    const float v10 = w3[(size_t)(k0 + 8) * 256 + gcol];
    const float v11 = w3[(size_t)(k0 + 9) * 256 + gcol];
    __half2 h0 = __floats2half2_rn(v00, v01);
    __half2 h1 = __floats2half2_rn(v10, v11);
    __half2 l0 = __floats2half2_rn((v00 - __low2float(h0)) * LO_SCALE,
                                   (v01 - __high2float(h0)) * LO_SCALE);
    __half2 l1 = __floats2half2_rn((v10 - __low2float(h1)) * LO_SCALE,
                                   (v11 - __high2float(h1)) * LO_SCALE);
    g3h[L * 64 + lane * 2]     = *(u32*)&h0;
    g3h[L * 64 + lane * 2 + 1] = *(u32*)&h1;
    g3l[L * 64 + lane * 2]     = *(u32*)&l0;
    g3l[L * 64 + lane * 2 + 1] = *(u32*)&l1;
}
__global__ void w2frag_kernel(const float* __restrict__ w2) {
    const int gid = blockIdx.x * 128 + threadIdx.x;   // 2048 threads
    const int L = gid >> 5, lane = gid & 31;
    const int ks = L & 3, nt = (L >> 2) & 3, w = L >> 4;
    const int gcol = w * 32 + nt * 8 + (lane >> 2);
    const int k0 = 16 * ks + 2 * (lane & 3);
    u32 h0, l0, h1, l1;
    split2_bf(w2[(size_t)k0 * 128 + gcol],       w2[(size_t)(k0 + 1) * 128 + gcol], h0, l0);
    split2_bf(w2[(size_t)(k0 + 8) * 128 + gcol], w2[(size_t)(k0 + 9) * 128 + gcol], h1, l1);
    g2h[L * 64 + lane * 2]     = h0;
    g2h[L * 64 + lane * 2 + 1] = h1;
    g2l[L * 64 + lane * 2]     = l0;
    g2l[L * 64 + lane * 2 + 1] = l1;
}

// ---------------------------------------------------------------------------
// Point branch: block = one object, 128 threads, two 64-point halves.
//  L1: FFMA -> h1 bf16 hi/lo split in shared.
//  L2: mma.sync bf16 (3 products) -> relu -> h2 fp16 single in shared.
//  L3: mma.sync fp16, 2 products (B hi + scaled-lo, separate fp32 acc);
//      A via ldmatrix (single buffer); max-pool in regs -> feat_s.
// ---------------------------------------------------------------------------
__global__ __launch_bounds__(128) void point_branch_kernel(
    const float* __restrict__ pts,
    const float* __restrict__ w1, const float* __restrict__ b1,
    const float* __restrict__ b2, const float* __restrict__ b3,
    const float* __restrict__ oew, const float* __restrict__ oeb,
    float* __restrict__ out)
{
    __shared__ u32 h2s[64 * H2ST];   // 4352 w = 17408 B (fp16x2)
    __shared__ u32 h1h[64 * H1ST];   // 2304 w
    __shared__ u32 h1l[64 * H1ST];   // 2304 w
    __shared__ float feat_s[256];

    const u32 h2s_u = smem_u32(h2s);
    const u32 h1h_u = smem_u32(h1h), h1l_u = smem_u32(h1l);

    const int n    = blockIdx.x;
    const int t    = threadIdx.x;
    const int w_   = t >> 5;
    const int lane = t & 31;

    const int lm_row = lane & 15;
    const int lm_col = (lane >> 4) << 2;

#pragma unroll 1
    for (int hf = 0; hf < 2; ++hf) {
        __syncthreads();

        // ================= layer 1: 64 points -> h1 split (bf16) ============
#pragma unroll
        for (int pg2 = 0; pg2 < 2; ++pg2) {
            const int pl = t & 31;
            const int j0 = (t >> 5) * 16;
            const int row = pg2 * 32 + pl;
            const size_t pb = ((size_t)n * PPT + (size_t)(hf * 2 + pg2) * 32 + pl) * 3;
            const float x = pts[pb + 0], y = pts[pb + 1], z = pts[pb + 2];
            float v[16];
#pragma unroll
            for (int j = 0; j < 16; ++j) {
                const int jj = j0 + j;
                float r = fmaf(x, __ldg(w1 + jj), fmaf(y, __ldg(w1 + 64 + jj), fmaf(z, __ldg(w1 + 128 + jj), __ldg(b1 + jj))));
                v[j] = fmaxf(r, 0.0f);
            }
            u32 hw[8], lw[8];
#pragma unroll
            for (int q = 0; q < 8; ++q) split2_bf(v[2 * q], v[2 * q + 1], hw[q], lw[q]);
            const int wb = row * H1ST + (j0 >> 1);
            *(uint4*)&h1h[wb]     = make_uint4(hw[0], hw[1], hw[2], hw[3]);
            *(uint4*)&h1h[wb + 4] = make_uint4(hw[4], hw[5], hw[6], hw[7]);
            *(uint4*)&h1l[wb]     = make_uint4(lw[0], lw[1], lw[2], lw[3]);
            *(uint4*)&h1l[wb + 4] = make_uint4(lw[4], lw[5], lw[6], lw[7]);
        }
        __syncthreads();

        // ================= layer 2: bf16 mma (3 products) -> h2 fp16 ========
#pragma unroll 1
        for (int nt = 0; nt < 4; ++nt) {
            const u32 lb = (u32)(((w_ * 4 + nt) * 4) * 64 + lane * 2);
            uint2 bh[4], bl[4];
#pragma unroll
            for (int ks = 0; ks < 4; ++ks) {
                bh[ks] = __ldg((const uint2*)(g2h + lb + ks * 64));
                bl[ks] = __ldg((const uint2*)(g2l + lb + ks * 64));
            }
            const float2 bb = __ldg((const float2*)(b2 + w_ * 32 + nt * 8 + 2 * (lane & 3)));

#pragma unroll
            for (int mt = 0; mt < 4; ++mt) {
                float acc[4] = { bb.x, bb.y, bb.x, bb.y };
#pragma unroll
                for (int ks = 0; ks < 4; ++ks) {
                    const u32 aoff = (u32)(((mt * 16 + lm_row) * H1ST + ks * 8 + lm_col) * 4);
                    u32 ah0, ah1, ah2, ah3, al0, al1, al2, al3;
                    ldsm_x4(ah0, ah1, ah2, ah3, h1h_u + aoff);
                    ldsm_x4(al0, al1, al2, al3, h1l_u + aoff);
                    mma_bf16(acc, ah0, ah1, ah2, ah3, bh[ks].x, bh[ks].y);
                    mma_bf16(acc, ah0, ah1, ah2, ah3, bl[ks].x, bl[ks].y);
                    mma_bf16(acc, al0, al1, al2, al3, bh[ks].x, bh[ks].y);
                }
                const int r0 = mt * 16 + (lane >> 2);
                const int wd = w_ * 16 + nt * 4 + (lane & 3);
                __half2 p0 = __floats2half2_rn(fmaxf(acc[0], 0.0f), fmaxf(acc[1], 0.0f));
                __half2 p1 = __floats2half2_rn(fmaxf(acc[2], 0.0f), fmaxf(acc[3], 0.0f));
                h2s[r0 * H2ST + wd]       = *(u32*)&p0;
                h2s[(r0 + 8) * H2ST + wd] = *(u32*)&p1;
            }
        }
        __syncthreads();

        // ================= layer 3: fp16 mma (2 products) ====================
#pragma unroll 1
        for (int np = 0; np < 4; ++np) {
            uint2 bh[2][8], bl[2][8];
#pragma unroll
            for (int nt = 0; nt < 2; ++nt) {
                const u32 lb = (u32)((((np * 4 + w_) * 2 + nt) * 8) * 64 + lane * 2);
#pragma unroll
                for (int ks = 0; ks < 8; ++ks) {
                    bh[nt][ks] = __ldg((const uint2*)(g3h + lb + ks * 64));
                    bl[nt][ks] = __ldg((const uint2*)(g3l + lb + ks * 64));
                }
            }

            float rm[2][2] = { {-3.0e38f, -3.0e38f}, {-3.0e38f, -3.0e38f} };

#pragma unroll
            for (int mt = 0; mt < 4; ++mt) {
                float acch[2][4], accl[2][4];
#pragma unroll
                for (int nt = 0; nt < 2; ++nt)
#pragma unroll
                    for (int q = 0; q < 4; ++q) { acch[nt][q] = 0.0f; accl[nt][q] = 0.0f; }

#pragma unroll
                for (int ks = 0; ks < 8; ++ks) {
                    const u32 aoff = (u32)(((mt * 16 + lm_row) * H2ST + ks * 8 + lm_col) * 4);
                    u32 a0, a1, a2, a3;
                    ldsm_x4(a0, a1, a2, a3, h2s_u + aoff);
#pragma unroll
                    for (int nt = 0; nt < 2; ++nt) {
                        mma_f16(acch[nt], a0, a1, a2, a3, bh[nt][ks].x, bh[nt][ks].y);
                        mma_f16(accl[nt], a0, a1, a2, a3, bl[nt][ks].x, bl[nt][ks].y);
                    }
                }
#pragma unroll
                for (int nt = 0; nt < 2; ++nt) {
                    const float c0 = fmaf(accl[nt][0], LO_INV, acch[nt][0]);
                    const float c1 = fmaf(accl[nt][1], LO_INV, acch[nt][1]);
                    const float c2 = fmaf(accl[nt][2], LO_INV, acch[nt][2]);
                    const float c3 = fmaf(accl[nt][3], LO_INV, acch[nt][3]);
                    rm[nt][0] = fmaxf(rm[nt][0], fmaxf(c0, c2));
                    rm[nt][1] = fmaxf(rm[nt][1], fmaxf(c1, c3));
                }
            }

#pragma unroll
            for (int nt = 0; nt < 2; ++nt) {
#pragma unroll
                for (int j = 0; j < 2; ++j) {
                    float m = rm[nt][j];
                    m = fmaxf(m, __shfl_xor_sync(0xffffffffu, m, 4));
                    m = fmaxf(m, __shfl_xor_sync(0xffffffffu, m, 8));
                    m = fmaxf(m, __shfl_xor_sync(0xffffffffu, m, 16));
                    if (lane < 4) {
                        const int col = np * 64 + w_ * 16 + nt * 8 + 2 * lane + j;
                        if (hf == 0) feat_s[col] = m;
                        else         feat_s[col] = fmaxf(feat_s[col], m) + __ldg(b3 + col);
                    }
                }
            }
        }
    }
    __syncthreads();

    // ---- pt_out = feat @ oe_w + oe_b
    if (t < EMB) {
        float acc = __ldg(oeb + t);
#pragma unroll 4
        for (int k = 0; k < 256; k += 4) {
            const float4 f = *(const float4*)&feat_s[k];
            acc = fmaf(f.x, __ldg(oew + (size_t)(k + 0) * EMB + t), acc);
            acc = fmaf(f.y, __ldg(oew + (size_t)(k + 1) * EMB + t), acc);
            acc = fmaf(f.z, __ldg(oew + (size_t)(k + 2) * EMB + t), acc);
            acc = fmaf(f.w, __ldg(oew + (size_t)(k + 3) * EMB + t), acc);
        }
        out[(size_t)n * OUTW + EMB + t] = acc;
    }
}

// ---------------------------------------------------------------------------
// Node branch (unchanged)
// ---------------------------------------------------------------------------
__global__ __launch_bounds__(256) void node_branch_kernel(
    const float* __restrict__ srcf,
    const float* __restrict__ reff,
    const void*  __restrict__ counts_raw,
    const float* __restrict__ w1, const float* __restrict__ b1,
    const float* __restrict__ w2, const float* __restrict__ b2,
    const float* __restrict__ sew, const float* __restrict__ seb,
    float* __restrict__ out)
{
    __shared__ float xs[8 * 260];
    __shared__ float hs[8 * 260];
    __shared__ int srow[8];
    __shared__ int sflag[8];

    const int t = threadIdx.x;
    const long long o0 = (long long)blockIdx.x * 8;

    if (t < 8) {
        const int* c32 = (const int*)counts_raw;
        const bool is64 = (c32[1] == 0 && c32[3] == 0);
        const long long o = o0 + t;
        long long cum = 0, ssum = 0, rsum = 0, idx = 0;
        int flag = 0;
        for (int b = 0; b < NB; ++b) {
            long long sc, rc;
            if (is64) { sc = ((const long long*)counts_raw)[2 * b]; rc = ((const long long*)counts_raw)[2 * b + 1]; }
            else      { sc = c32[2 * b]; rc = c32[2 * b + 1]; }
            const long long tot = sc + rc;
            if (o < cum + tot) {
                const long long off = o - cum;
                if (off < sc) { flag = 0; idx = ssum + off; }
                else          { flag = 1; idx = rsum + (off - sc); }
                break;
            }
            cum += tot; ssum += sc; rsum += rc;
        }
        srow[t] = (int)idx; sflag[t] = flag;
    }
    __syncthreads();

#pragma unroll
    for (int r = 0; r < 8; ++r) {
        const float* base = sflag[r] ? reff : srcf;
        xs[r * 260 + t] = base[(size_t)srow[r] * FEAT + t];
    }
    __syncthreads();

    float acc[8];
    {
        const float bv = __ldg(b1 + t);
#pragma unroll
        for (int r = 0; r < 8; ++r) acc[r] = bv;
#pragma unroll 1
        for (int k = 0; k < 256; k += 4) {
            const float w0 = __ldg(w1 + (size_t)(k + 0) * 256 + t);
            const float wq1 = __ldg(w1 + (size_t)(k + 1) * 256 + t);
            const float wq2 = __ldg(w1 + (size_t)(k + 2) * 256 + t);
            const float wq3 = __ldg(w1 + (size_t)(k + 3) * 256 + t);
#pragma unroll
            for (int r = 0; r < 8; ++r) {
                float4 xv = *(const float4*)&xs[r * 260 + k];
                acc[r] = fmaf(xv.x, w0, acc[r]);
                acc[r] = fmaf(xv.y, wq1, acc[r]);
                acc[r] = fmaf(xv.z, wq2, acc[r]);
                acc[r] = fmaf(xv.w, wq3, acc[r]);
            }
        }
#pragma unroll
        for (int r = 0; r < 8; ++r) hs[r * 260 + t] = fmaxf(acc[r], 0.0f);
    }
    __syncthreads();
    {
        const float bv = __ldg(b2 + t);
#pragma unroll
        for (int r = 0; r < 8; ++r) acc[r] = bv;
#pragma unroll 1
        for (int k = 0; k < 256; k += 4) {
            const float w0 = __ldg(w2 + (size_t)(k + 0) * 256 + t);
            const float wq1 = __ldg(w2 + (size_t)(k + 1) * 256 + t);
            const float wq2 = __ldg(w2 + (size_t)(k + 2) * 256 + t);
            const float wq3 = __ldg(w2 + (size_t)(k + 3) * 256 + t);
#pragma unroll
            for (int r = 0; r < 8; ++r) {
                float4 xv = *(const float4*)&hs[r * 260 + k];
                acc[r] = fmaf(xv.x, w0, acc[r]);
                acc[r] = fmaf(xv.y, wq1, acc[r]);
                acc[r] = fmaf(xv.z, wq2, acc[r]);
                acc[r] = fmaf(xv.w, wq3, acc[r]);
            }
        }
#pragma unroll
        for (int r = 0; r < 8; ++r) xs[r * 260 + t] = acc[r];
    }
    __syncthreads();

    if (t < EMB) {
        float accs[8];
        const float bv = __ldg(seb + t);
#pragma unroll
        for (int r = 0; r < 8; ++r) accs[r] = bv;
#pragma unroll 1
        for (int k = 0; k < 256; k += 4) {
            const float w0 = __ldg(sew + (size_t)(k + 0) * EMB + t);
            const float wq1 = __ldg(sew + (size_t)(k + 1) * EMB + t);
            const float wq2 = __ldg(sew + (size_t)(k + 2) * EMB + t);
            const float wq3 = __ldg(sew + (size_t)(k + 3) * EMB + t);
#pragma unroll
            for (int r = 0; r < 8; ++r) {
                float4 ev = *(const float4*)&xs[r * 260 + k];
                accs[r] = fmaf(ev.x, w0, accs[r]);
                accs[r] = fmaf(ev.y, wq1, accs[r]);
                accs[r] = fmaf(ev.z, wq2, accs[r]);
                accs[r] = fmaf(ev.w, wq3, accs[r]);
            }
        }
#pragma unroll
        for (int r = 0; r < 8; ++r)
            out[(size_t)(o0 + r) * OUTW + t] = accs[r];
    }
}

extern "C" void kernel_launch(void* const* d_in, const int* in_sizes, int n_in,
                              void* d_out, int out_size)
{
    const float* pts    = (const float*)d_in[0];
    const float* srcf   = (const float*)d_in[1];
    const float* reff   = (const float*)d_in[2];
    const void*  counts = d_in[3];
    const float* sg_w1  = (const float*)d_in[6];
    const float* sg_b1  = (const float*)d_in[7];
    const float* sg_w2  = (const float*)d_in[8];
    const float* sg_b2  = (const float*)d_in[9];
    const float* se_w   = (const float*)d_in[10];
    const float* se_b   = (const float*)d_in[11];
    const float* p_w1   = (const float*)d_in[12];
    const float* p_b1   = (const float*)d_in[13];
    const float* p_w2   = (const float*)d_in[14];
    const float* p_b2   = (const float*)d_in[15];
    const float* p_w3   = (const float*)d_in[16];
    const float* p_b3   = (const float*)d_in[17];
    const float* oe_w   = (const float*)d_in[18];
    const float* oe_b   = (const float*)d_in[19];
    float* out = (float*)d_out;

    w3frag_kernel<<<64, 128>>>(p_w3);
    w2frag_kernel<<<16, 128>>>(p_w2);
    node_branch_kernel<<<N_TOT / 8, 256>>>(srcf, reff, counts,
                                           sg_w1, sg_b1, sg_w2, sg_b2,
                                           se_w, se_b, out);
    point_branch_kernel<<<N_TOT, 128>>>(pts, p_w1, p_b1, p_b2, p_b3,
                                        oe_w, oe_b, out);
}

// round 10
// speedup vs baseline: 5.7940x; 1.6224x over previous
#include <cuda_runtime.h>
#include <cuda_fp16.h>
#include <stdint.h>

#define NB    16
#define N_TOT 16384
#define PPT   128
#define FEAT  256
#define EMB   100
#define OUTW  200

typedef unsigned long long u64;
typedef unsigned int u32;

// ---------------- mma / ldmatrix (portable ISA) ----------------
__device__ __forceinline__ void mma_f16(float* c,
                                        u32 a0, u32 a1, u32 a2, u32 a3,
                                        u32 b0, u32 b1) {
    asm("mma.sync.aligned.m16n8k16.row.col.f32.f16.f16.f32 "
        "{%0,%1,%2,%3}, {%4,%5,%6,%7}, {%8,%9}, {%0,%1,%2,%3};"
        : "+f"(c[0]), "+f"(c[1]), "+f"(c[2]), "+f"(c[3])
        : "r"(a0), "r"(a1), "r"(a2), "r"(a3), "r"(b0), "r"(b1));
}
__device__ __forceinline__ void ldsm_x4(u32& r0, u32& r1, u32& r2, u32& r3, u32 saddr) {
    asm volatile("ldmatrix.sync.aligned.m8n8.x4.shared.b16 {%0,%1,%2,%3}, [%4];"
                 : "=r"(r0), "=r"(r1), "=r"(r2), "=r"(r3) : "r"(saddr));
}
__device__ __forceinline__ u32 smem_u32(const void* p) {
    u32 a; asm("{ .reg .u64 t; cvta.to.shared.u64 t, %1; cvt.u32.u64 %0, t; }" : "=r"(a) : "l"(p));
    return a;
}

#define H1ST 36   // h1 rows: 32 data words (fp16x2) + 4 pad
#define H2ST 68   // h2 rows: 64 data words (fp16x2) + 4 pad

// Coalesced fp16 B-fragment layouts: group L -> 32 lanes x uint2 contiguous.
// W3: L = ((np*4 + w)*2 + nt)*8 + ks  (256 groups)
__device__ u32 g3h[256 * 64];
// W2: L = (w*4 + nt)*4 + ks           (64 groups)
__device__ u32 g2h[64 * 64];

__global__ void w3frag_kernel(const float* __restrict__ w3) {
    const int gid = blockIdx.x * 128 + threadIdx.x;   // 8192 threads
    const int L = gid >> 5, lane = gid & 31;
    const int ks = L & 7, nt = (L >> 3) & 1, w = (L >> 4) & 3, np = L >> 6;
    const int gcol = np * 64 + w * 16 + nt * 8 + (lane >> 2);
    const int k0 = 16 * ks + 2 * (lane & 3);
    __half2 h0 = __floats2half2_rn(w3[(size_t)k0 * 256 + gcol],
                                   w3[(size_t)(k0 + 1) * 256 + gcol]);
    __half2 h1 = __floats2half2_rn(w3[(size_t)(k0 + 8) * 256 + gcol],
                                   w3[(size_t)(k0 + 9) * 256 + gcol]);
    g3h[L * 64 + lane * 2]     = *(u32*)&h0;
    g3h[L * 64 + lane * 2 + 1] = *(u32*)&h1;
}
__global__ void w2frag_kernel(const float* __restrict__ w2) {
    const int gid = blockIdx.x * 128 + threadIdx.x;   // 2048 threads
    const int L = gid >> 5, lane = gid & 31;
    const int ks = L & 3, nt = (L >> 2) & 3, w = L >> 4;
    const int gcol = w * 32 + nt * 8 + (lane >> 2);
    const int k0 = 16 * ks + 2 * (lane & 3);
    __half2 h0 = __floats2half2_rn(w2[(size_t)k0 * 128 + gcol],
                                   w2[(size_t)(k0 + 1) * 128 + gcol]);
    __half2 h1 = __floats2half2_rn(w2[(size_t)(k0 + 8) * 128 + gcol],
                                   w2[(size_t)(k0 + 9) * 128 + gcol]);
    g2h[L * 64 + lane * 2]     = *(u32*)&h0;
    g2h[L * 64 + lane * 2 + 1] = *(u32*)&h1;
}

// ---------------------------------------------------------------------------
// Point branch: block = one object, 128 threads, two 64-point halves.
//  L1: FFMA -> h1 fp16 in shared.
//  L2: mma.sync fp16 single product, mt-outer (A loaded once per mt).
//  L3: mma.sync fp16 single product, np processed in pairs (A loaded 2x).
//  Max-pool in regs -> feat_s; pt_out epilogue.
// ---------------------------------------------------------------------------
__global__ __launch_bounds__(128) void point_branch_kernel(
    const float* __restrict__ pts,
    const float* __restrict__ w1, const float* __restrict__ b1,
    const float* __restrict__ b2, const float* __restrict__ b3,
    const float* __restrict__ oew, const float* __restrict__ oeb,
    float* __restrict__ out)
{
    __shared__ u32 h2s[64 * H2ST];   // 17408 B
    __shared__ u32 h1s[64 * H1ST];   //  9216 B
    __shared__ float feat_s[256];

    const u32 h2s_u = smem_u32(h2s);
    const u32 h1s_u = smem_u32(h1s);

    const int n    = blockIdx.x;
    const int t    = threadIdx.x;
    const int w_   = t >> 5;
    const int lane = t & 31;

    const int lm_row = lane & 15;
    const int lm_col = (lane >> 4) << 2;

#pragma unroll 1
    for (int hf = 0; hf < 2; ++hf) {
        __syncthreads();

        // ================= layer 1: 64 points -> h1 fp16 =====================
#pragma unroll
        for (int pg2 = 0; pg2 < 2; ++pg2) {
            const int pl = t & 31;
            const int j0 = (t >> 5) * 16;
            const int row = pg2 * 32 + pl;
            const size_t pb = ((size_t)n * PPT + (size_t)(hf * 2 + pg2) * 32 + pl) * 3;
            const float x = pts[pb + 0], y = pts[pb + 1], z = pts[pb + 2];
            u32 hw[8];
#pragma unroll
            for (int q = 0; q < 8; ++q) {
                const int jj = j0 + 2 * q;
                float r0 = fmaf(x, __ldg(w1 + jj),     fmaf(y, __ldg(w1 + 64 + jj),     fmaf(z, __ldg(w1 + 128 + jj),     __ldg(b1 + jj))));
                float r1 = fmaf(x, __ldg(w1 + jj + 1), fmaf(y, __ldg(w1 + 64 + jj + 1), fmaf(z, __ldg(w1 + 128 + jj + 1), __ldg(b1 + jj + 1))));
                __half2 h = __floats2half2_rn(fmaxf(r0, 0.0f), fmaxf(r1, 0.0f));
                hw[q] = *(u32*)&h;
            }
            const int wb = row * H1ST + (j0 >> 1);
            *(uint4*)&h1s[wb]     = make_uint4(hw[0], hw[1], hw[2], hw[3]);
            *(uint4*)&h1s[wb + 4] = make_uint4(hw[4], hw[5], hw[6], hw[7]);
        }
        __syncthreads();

        // ================= layer 2: fp16 mma, mt-outer ======================
        {
            uint2 bh[4][4];      // [nt][ks]
            float2 bb[4];
#pragma unroll
            for (int nt = 0; nt < 4; ++nt) {
                const u32 lb = (u32)(((w_ * 4 + nt) * 4) * 64 + lane * 2);
#pragma unroll
                for (int ks = 0; ks < 4; ++ks)
                    bh[nt][ks] = __ldg((const uint2*)(g2h + lb + ks * 64));
                bb[nt] = __ldg((const float2*)(b2 + w_ * 32 + nt * 8 + 2 * (lane & 3)));
            }

#pragma unroll
            for (int mt = 0; mt < 4; ++mt) {
                u32 a[4][4];
#pragma unroll
                for (int ks = 0; ks < 4; ++ks) {
                    const u32 aoff = (u32)(((mt * 16 + lm_row) * H1ST + ks * 8 + lm_col) * 4);
                    ldsm_x4(a[ks][0], a[ks][1], a[ks][2], a[ks][3], h1s_u + aoff);
                }
#pragma unroll
                for (int nt = 0; nt < 4; ++nt) {
                    float acc[4] = { bb[nt].x, bb[nt].y, bb[nt].x, bb[nt].y };
#pragma unroll
                    for (int ks = 0; ks < 4; ++ks)
                        mma_f16(acc, a[ks][0], a[ks][1], a[ks][2], a[ks][3],
                                bh[nt][ks].x, bh[nt][ks].y);
                    const int r0 = mt * 16 + (lane >> 2);
                    const int wd = w_ * 16 + nt * 4 + (lane & 3);
                    __half2 p0 = __floats2half2_rn(fmaxf(acc[0], 0.0f), fmaxf(acc[1], 0.0f));
                    __half2 p1 = __floats2half2_rn(fmaxf(acc[2], 0.0f), fmaxf(acc[3], 0.0f));
                    h2s[r0 * H2ST + wd]       = *(u32*)&p0;
                    h2s[(r0 + 8) * H2ST + wd] = *(u32*)&p1;
                }
            }
        }
        __syncthreads();

        // ================= layer 3: fp16 mma, np pairs ======================
#pragma unroll 1
        for (int npg = 0; npg < 2; ++npg) {
            uint2 bh[2][2][8];   // [p][nt][ks]
#pragma unroll
            for (int p = 0; p < 2; ++p)
#pragma unroll
                for (int nt = 0; nt < 2; ++nt) {
                    const int np = npg * 2 + p;
                    const u32 lb = (u32)((((np * 4 + w_) * 2 + nt) * 8) * 64 + lane * 2);
#pragma unroll
                    for (int ks = 0; ks < 8; ++ks)
                        bh[p][nt][ks] = __ldg((const uint2*)(g3h + lb + ks * 64));
                }

            float rm[2][2][2];
#pragma unroll
            for (int p = 0; p < 2; ++p)
#pragma unroll
                for (int nt = 0; nt < 2; ++nt) {
                    rm[p][nt][0] = -3.0e38f; rm[p][nt][1] = -3.0e38f;
                }

#pragma unroll
            for (int mt = 0; mt < 4; ++mt) {
                u32 a[8][4];
#pragma unroll
                for (int ks = 0; ks < 8; ++ks) {
                    const u32 aoff = (u32)(((mt * 16 + lm_row) * H2ST + ks * 8 + lm_col) * 4);
                    ldsm_x4(a[ks][0], a[ks][1], a[ks][2], a[ks][3], h2s_u + aoff);
                }
#pragma unroll
                for (int p = 0; p < 2; ++p)
#pragma unroll
                    for (int nt = 0; nt < 2; ++nt) {
                        float acc[4] = { 0.0f, 0.0f, 0.0f, 0.0f };
#pragma unroll
                        for (int ks = 0; ks < 8; ++ks)
                            mma_f16(acc, a[ks][0], a[ks][1], a[ks][2], a[ks][3],
                                    bh[p][nt][ks].x, bh[p][nt][ks].y);
                        rm[p][nt][0] = fmaxf(rm[p][nt][0], fmaxf(acc[0], acc[2]));
                        rm[p][nt][1] = fmaxf(rm[p][nt][1], fmaxf(acc[1], acc[3]));
                    }
            }

#pragma unroll
            for (int p = 0; p < 2; ++p)
#pragma unroll
                for (int nt = 0; nt < 2; ++nt)
#pragma unroll
                    for (int j = 0; j < 2; ++j) {
                        float m = rm[p][nt][j];
                        m = fmaxf(m, __shfl_xor_sync(0xffffffffu, m, 4));
                        m = fmaxf(m, __shfl_xor_sync(0xffffffffu, m, 8));
                        m = fmaxf(m, __shfl_xor_sync(0xffffffffu, m, 16));
                        if (lane < 4) {
                            const int col = (npg * 2 + p) * 64 + w_ * 16 + nt * 8 + 2 * lane + j;
                            if (hf == 0) feat_s[col] = m;
                            else         feat_s[col] = fmaxf(feat_s[col], m) + __ldg(b3 + col);
                        }
                    }
        }
    }
    __syncthreads();

    // ---- pt_out = feat @ oe_w + oe_b
    if (t < EMB) {
        float acc = __ldg(oeb + t);
#pragma unroll 4
        for (int k = 0; k < 256; k += 4) {
            const float4 f = *(const float4*)&feat_s[k];
            acc = fmaf(f.x, __ldg(oew + (size_t)(k + 0) * EMB + t), acc);
            acc = fmaf(f.y, __ldg(oew + (size_t)(k + 1) * EMB + t), acc);
            acc = fmaf(f.z, __ldg(oew + (size_t)(k + 2) * EMB + t), acc);
            acc = fmaf(f.w, __ldg(oew + (size_t)(k + 3) * EMB + t), acc);
        }
        out[(size_t)n * OUTW + EMB + t] = acc;
    }
}

// ---------------------------------------------------------------------------
// Node branch (unchanged)
// ---------------------------------------------------------------------------
__global__ __launch_bounds__(256) void node_branch_kernel(
    const float* __restrict__ srcf,
    const float* __restrict__ reff,
    const void*  __restrict__ counts_raw,
    const float* __restrict__ w1, const float* __restrict__ b1,
    const float* __restrict__ w2, const float* __restrict__ b2,
    const float* __restrict__ sew, const float* __restrict__ seb,
    float* __restrict__ out)
{
    __shared__ float xs[8 * 260];
    __shared__ float hs[8 * 260];
    __shared__ int srow[8];
    __shared__ int sflag[8];

    const int t = threadIdx.x;
    const long long o0 = (long long)blockIdx.x * 8;

    if (t < 8) {
        const int* c32 = (const int*)counts_raw;
        const bool is64 = (c32[1] == 0 && c32[3] == 0);
        const long long o = o0 + t;
        long long cum = 0, ssum = 0, rsum = 0, idx = 0;
        int flag = 0;
        for (int b = 0; b < NB; ++b) {
            long long sc, rc;
            if (is64) { sc = ((const long long*)counts_raw)[2 * b]; rc = ((const long long*)counts_raw)[2 * b + 1]; }
            else      { sc = c32[2 * b]; rc = c32[2 * b + 1]; }
            const long long tot = sc + rc;
            if (o < cum + tot) {
                const long long off = o - cum;
                if (off < sc) { flag = 0; idx = ssum + off; }
                else          { flag = 1; idx = rsum + (off - sc); }
                break;
            }
            cum += tot; ssum += sc; rsum += rc;
        }
        srow[t] = (int)idx; sflag[t] = flag;
    }
    __syncthreads();

#pragma unroll
    for (int r = 0; r < 8; ++r) {
        const float* base = sflag[r] ? reff : srcf;
        xs[r * 260 + t] = base[(size_t)srow[r] * FEAT + t];
    }
    __syncthreads();

    float acc[8];
    {
        const float bv = __ldg(b1 + t);
#pragma unroll
        for (int r = 0; r < 8; ++r) acc[r] = bv;
#pragma unroll 1
        for (int k = 0; k < 256; k += 4) {
            const float w0 = __ldg(w1 + (size_t)(k + 0) * 256 + t);
            const float wq1 = __ldg(w1 + (size_t)(k + 1) * 256 + t);
            const float wq2 = __ldg(w1 + (size_t)(k + 2) * 256 + t);
            const float wq3 = __ldg(w1 + (size_t)(k + 3) * 256 + t);
#pragma unroll
            for (int r = 0; r < 8; ++r) {
                float4 xv = *(const float4*)&xs[r * 260 + k];
                acc[r] = fmaf(xv.x, w0, acc[r]);
                acc[r] = fmaf(xv.y, wq1, acc[r]);
                acc[r] = fmaf(xv.z, wq2, acc[r]);
                acc[r] = fmaf(xv.w, wq3, acc[r]);
            }
        }
#pragma unroll
        for (int r = 0; r < 8; ++r) hs[r * 260 + t] = fmaxf(acc[r], 0.0f);
    }
    __syncthreads();
    {
        const float bv = __ldg(b2 + t);
#pragma unroll
        for (int r = 0; r < 8; ++r) acc[r] = bv;
#pragma unroll 1
        for (int k = 0; k < 256; k += 4) {
            const float w0 = __ldg(w2 + (size_t)(k + 0) * 256 + t);
            const float wq1 = __ldg(w2 + (size_t)(k + 1) * 256 + t);
            const float wq2 = __ldg(w2 + (size_t)(k + 2) * 256 + t);
            const float wq3 = __ldg(w2 + (size_t)(k + 3) * 256 + t);
#pragma unroll
            for (int r = 0; r < 8; ++r) {
                float4 xv = *(const float4*)&hs[r * 260 + k];
                acc[r] = fmaf(xv.x, w0, acc[r]);
                acc[r] = fmaf(xv.y, wq1, acc[r]);
                acc[r] = fmaf(xv.z, wq2, acc[r]);
                acc[r] = fmaf(xv.w, wq3, acc[r]);
            }
        }
#pragma unroll
        for (int r = 0; r < 8; ++r) xs[r * 260 + t] = acc[r];
    }
    __syncthreads();

    if (t < EMB) {
        float accs[8];
        const float bv = __ldg(seb + t);
#pragma unroll
        for (int r = 0; r < 8; ++r) accs[r] = bv;
#pragma unroll 1
        for (int k = 0; k < 256; k += 4) {
            const float w0 = __ldg(sew + (size_t)(k + 0) * EMB + t);
            const float wq1 = __ldg(sew + (size_t)(k + 1) * EMB + t);
            const float wq2 = __ldg(sew + (size_t)(k + 2) * EMB + t);
            const float wq3 = __ldg(sew + (size_t)(k + 3) * EMB + t);
#pragma unroll
            for (int r = 0; r < 8; ++r) {
                float4 ev = *(const float4*)&xs[r * 260 + k];
                accs[r] = fmaf(ev.x, w0, accs[r]);
                accs[r] = fmaf(ev.y, wq1, accs[r]);
                accs[r] = fmaf(ev.z, wq2, accs[r]);
                accs[r] = fmaf(ev.w, wq3, accs[r]);
            }
        }
#pragma unroll
        for (int r = 0; r < 8; ++r)
            out[(size_t)(o0 + r) * OUTW + t] = accs[r];
    }
}

extern "C" void kernel_launch(void* const* d_in, const int* in_sizes, int n_in,
                              void* d_out, int out_size)
{
    const float* pts    = (const float*)d_in[0];
    const float* srcf   = (const float*)d_in[1];
    const float* reff   = (const float*)d_in[2];
    const void*  counts = d_in[3];
    const float* sg_w1  = (const float*)d_in[6];
    const float* sg_b1  = (const float*)d_in[7];
    const float* sg_w2  = (const float*)d_in[8];
    const float* sg_b2  = (const float*)d_in[9];
    const float* se_w   = (const float*)d_in[10];
    const float* se_b   = (const float*)d_in[11];
    const float* p_w1   = (const float*)d_in[12];
    const float* p_b1   = (const float*)d_in[13];
    const float* p_w2   = (const float*)d_in[14];
    const float* p_b2   = (const float*)d_in[15];
    const float* p_w3   = (const float*)d_in[16];
    const float* p_b3   = (const float*)d_in[17];
    const float* oe_w   = (const float*)d_in[18];
    const float* oe_b   = (const float*)d_in[19];
    float* out = (float*)d_out;

    w3frag_kernel<<<64, 128>>>(p_w3);
    w2frag_kernel<<<16, 128>>>(p_w2);
    node_branch_kernel<<<N_TOT / 8, 256>>>(srcf, reff, counts,
                                           sg_w1, sg_b1, sg_w2, sg_b2,
                                           se_w, se_b, out);
    point_branch_kernel<<<N_TOT, 128>>>(pts, p_w1, p_b1, p_b2, p_b3,
                                        oe_w, oe_b, out);
}

// round 11
// speedup vs baseline: 7.4634x; 1.2881x over previous
#include <cuda_runtime.h>
#include <cuda_fp16.h>
#include <stdint.h>

#define NB    16
#define N_TOT 16384
#define PPT   128
#define FEAT  256
#define EMB   100
#define OUTW  200

typedef unsigned long long u64;
typedef unsigned int u32;

// ---------------- mma / ldmatrix (portable ISA) ----------------
__device__ __forceinline__ void mma_f16(float* c,
                                        u32 a0, u32 a1, u32 a2, u32 a3,
                                        u32 b0, u32 b1) {
    asm("mma.sync.aligned.m16n8k16.row.col.f32.f16.f16.f32 "
        "{%0,%1,%2,%3}, {%4,%5,%6,%7}, {%8,%9}, {%0,%1,%2,%3};"
        : "+f"(c[0]), "+f"(c[1]), "+f"(c[2]), "+f"(c[3])
        : "r"(a0), "r"(a1), "r"(a2), "r"(a3), "r"(b0), "r"(b1));
}
__device__ __forceinline__ void ldsm_x4(u32& r0, u32& r1, u32& r2, u32& r3, u32 saddr) {
    asm volatile("ldmatrix.sync.aligned.m8n8.x4.shared.b16 {%0,%1,%2,%3}, [%4];"
                 : "=r"(r0), "=r"(r1), "=r"(r2), "=r"(r3) : "r"(saddr));
}
__device__ __forceinline__ u32 smem_u32(const void* p) {
    u32 a; asm("{ .reg .u64 t; cvta.to.shared.u64 t, %1; cvt.u32.u64 %0, t; }" : "=r"(a) : "l"(p));
    return a;
}

#define H1ST 36   // h1 rows: 32 data words (fp16x2) + 4 pad
#define H2ST 68   // h2 rows: 64 data words (fp16x2) + 4 pad
#define NST  132  // node rows: 128 data words (fp16x2) + 4 pad

// Coalesced fp16 B-fragment stores: group L -> 32 lanes x uint2 contiguous.
__device__ u32 g3h[256 * 64];   // W3 point:  L = ((np*4+w)*2+nt)*8 + ks
__device__ u32 g2h[64 * 64];    // W2 point:  L = (w*4+nt)*4 + ks
__device__ u32 g_n1[512 * 64];  // sg_w1:     L = ntg*16 + ks (ntg 0..31)
__device__ u32 g_n2[512 * 64];  // sg_w2:     same layout
__device__ u32 g_se[208 * 64];  // se_w:      L = nt*16 + ks (nt 0..12, col<100 else 0)

// One merged precompute kernel: grid 388 x 128.
__global__ void frag_kernel(const float* __restrict__ pw2, const float* __restrict__ pw3,
                            const float* __restrict__ n1,  const float* __restrict__ n2,
                            const float* __restrict__ sew)
{
    const int bid = blockIdx.x;
    if (bid < 64) {                      // point W3: 8192 threads
        const int gid = bid * 128 + threadIdx.x;
        const int L = gid >> 5, lane = gid & 31;
        const int ks = L & 7, nt = (L >> 3) & 1, w = (L >> 4) & 3, np = L >> 6;
        const int gcol = np * 64 + w * 16 + nt * 8 + (lane >> 2);
        const int k0 = 16 * ks + 2 * (lane & 3);
        __half2 h0 = __floats2half2_rn(pw3[(size_t)k0 * 256 + gcol],
                                       pw3[(size_t)(k0 + 1) * 256 + gcol]);
        __half2 h1 = __floats2half2_rn(pw3[(size_t)(k0 + 8) * 256 + gcol],
                                       pw3[(size_t)(k0 + 9) * 256 + gcol]);
        g3h[L * 64 + lane * 2]     = *(u32*)&h0;
        g3h[L * 64 + lane * 2 + 1] = *(u32*)&h1;
    } else if (bid < 80) {               // point W2: 2048 threads
        const int gid = (bid - 64) * 128 + threadIdx.x;
        const int L = gid >> 5, lane = gid & 31;
        const int ks = L & 3, nt = (L >> 2) & 3, w = L >> 4;
        const int gcol = w * 32 + nt * 8 + (lane >> 2);
        const int k0 = 16 * ks + 2 * (lane & 3);
        __half2 h0 = __floats2half2_rn(pw2[(size_t)k0 * 128 + gcol],
                                       pw2[(size_t)(k0 + 1) * 128 + gcol]);
        __half2 h1 = __floats2half2_rn(pw2[(size_t)(k0 + 8) * 128 + gcol],
                                       pw2[(size_t)(k0 + 9) * 128 + gcol]);
        g2h[L * 64 + lane * 2]     = *(u32*)&h0;
        g2h[L * 64 + lane * 2 + 1] = *(u32*)&h1;
    } else if (bid < 336) {              // node sg_w1/sg_w2: 32768 threads
        const int gid = (bid - 80) * 128 + threadIdx.x;
        const int sel = gid >= 16384;
        const float* w = sel ? n2 : n1;
        u32* dst = sel ? g_n2 : g_n1;
        const int g = gid & 16383;
        const int L = g >> 5, lane = g & 31;
        const int ks = L & 15, ntg = L >> 4;
        const int col = ntg * 8 + (lane >> 2);
        const int k0 = 16 * ks + 2 * (lane & 3);
        __half2 h0 = __floats2half2_rn(w[(size_t)k0 * 256 + col],
                                       w[(size_t)(k0 + 1) * 256 + col]);
        __half2 h1 = __floats2half2_rn(w[(size_t)(k0 + 8) * 256 + col],
                                       w[(size_t)(k0 + 9) * 256 + col]);
        dst[L * 64 + lane * 2]     = *(u32*)&h0;
        dst[L * 64 + lane * 2 + 1] = *(u32*)&h1;
    } else {                             // se_w: 6656 threads
        const int gid = (bid - 336) * 128 + threadIdx.x;
        if (gid < 6656) {
            const int L = gid >> 5, lane = gid & 31;
            const int ks = L & 15, nt = L >> 4;
            const int col = nt * 8 + (lane >> 2);
            const int k0 = 16 * ks + 2 * (lane & 3);
            const float v00 = (col < EMB) ? sew[(size_t)k0 * EMB + col] : 0.0f;
            const float v01 = (col < EMB) ? sew[(size_t)(k0 + 1) * EMB + col] : 0.0f;
            const float v10 = (col < EMB) ? sew[(size_t)(k0 + 8) * EMB + col] : 0.0f;
            const float v11 = (col < EMB) ? sew[(size_t)(k0 + 9) * EMB + col] : 0.0f;
            __half2 h0 = __floats2half2_rn(v00, v01);
            __half2 h1 = __floats2half2_rn(v10, v11);
            g_se[L * 64 + lane * 2]     = *(u32*)&h0;
            g_se[L * 64 + lane * 2 + 1] = *(u32*)&h1;
        }
    }
}

// ---------------------------------------------------------------------------
// Point branch (unchanged from R10 best)
// ---------------------------------------------------------------------------
__global__ __launch_bounds__(128) void point_branch_kernel(
    const float* __restrict__ pts,
    const float* __restrict__ w1, const float* __restrict__ b1,
    const float* __restrict__ b2, const float* __restrict__ b3,
    const float* __restrict__ oew, const float* __restrict__ oeb,
    float* __restrict__ out)
{
    __shared__ u32 h2s[64 * H2ST];
    __shared__ u32 h1s[64 * H1ST];
    __shared__ float feat_s[256];

    const u32 h2s_u = smem_u32(h2s);
    const u32 h1s_u = smem_u32(h1s);

    const int n    = blockIdx.x;
    const int t    = threadIdx.x;
    const int w_   = t >> 5;
    const int lane = t & 31;

    const int lm_row = lane & 15;
    const int lm_col = (lane >> 4) << 2;

#pragma unroll 1
    for (int hf = 0; hf < 2; ++hf) {
        __syncthreads();

#pragma unroll
        for (int pg2 = 0; pg2 < 2; ++pg2) {
            const int pl = t & 31;
            const int j0 = (t >> 5) * 16;
            const int row = pg2 * 32 + pl;
            const size_t pb = ((size_t)n * PPT + (size_t)(hf * 2 + pg2) * 32 + pl) * 3;
            const float x = pts[pb + 0], y = pts[pb + 1], z = pts[pb + 2];
            u32 hw[8];
#pragma unroll
            for (int q = 0; q < 8; ++q) {
                const int jj = j0 + 2 * q;
                float r0 = fmaf(x, __ldg(w1 + jj),     fmaf(y, __ldg(w1 + 64 + jj),     fmaf(z, __ldg(w1 + 128 + jj),     __ldg(b1 + jj))));
                float r1 = fmaf(x, __ldg(w1 + jj + 1), fmaf(y, __ldg(w1 + 64 + jj + 1), fmaf(z, __ldg(w1 + 128 + jj + 1), __ldg(b1 + jj + 1))));
                __half2 h = __floats2half2_rn(fmaxf(r0, 0.0f), fmaxf(r1, 0.0f));
                hw[q] = *(u32*)&h;
            }
            const int wb = row * H1ST + (j0 >> 1);
            *(uint4*)&h1s[wb]     = make_uint4(hw[0], hw[1], hw[2], hw[3]);
            *(uint4*)&h1s[wb + 4] = make_uint4(hw[4], hw[5], hw[6], hw[7]);
        }
        __syncthreads();

        {
            uint2 bh[4][4];
            float2 bb[4];
#pragma unroll
            for (int nt = 0; nt < 4; ++nt) {
                const u32 lb = (u32)(((w_ * 4 + nt) * 4) * 64 + lane * 2);
#pragma unroll
                for (int ks = 0; ks < 4; ++ks)
                    bh[nt][ks] = __ldg((const uint2*)(g2h + lb + ks * 64));
                bb[nt] = __ldg((const float2*)(b2 + w_ * 32 + nt * 8 + 2 * (lane & 3)));
            }

#pragma unroll
            for (int mt = 0; mt < 4; ++mt) {
                u32 a[4][4];
#pragma unroll
                for (int ks = 0; ks < 4; ++ks) {
                    const u32 aoff = (u32)(((mt * 16 + lm_row) * H1ST + ks * 8 + lm_col) * 4);
                    ldsm_x4(a[ks][0], a[ks][1], a[ks][2], a[ks][3], h1s_u + aoff);
                }
#pragma unroll
                for (int nt = 0; nt < 4; ++nt) {
                    float acc[4] = { bb[nt].x, bb[nt].y, bb[nt].x, bb[nt].y };
#pragma unroll
                    for (int ks = 0; ks < 4; ++ks)
                        mma_f16(acc, a[ks][0], a[ks][1], a[ks][2], a[ks][3],
                                bh[nt][ks].x, bh[nt][ks].y);
                    const int r0 = mt * 16 + (lane >> 2);
                    const int wd = w_ * 16 + nt * 4 + (lane & 3);
                    __half2 p0 = __floats2half2_rn(fmaxf(acc[0], 0.0f), fmaxf(acc[1], 0.0f));
                    __half2 p1 = __floats2half2_rn(fmaxf(acc[2], 0.0f), fmaxf(acc[3], 0.0f));
                    h2s[r0 * H2ST + wd]       = *(u32*)&p0;
                    h2s[(r0 + 8) * H2ST + wd] = *(u32*)&p1;
                }
            }
        }
        __syncthreads();

#pragma unroll 1
        for (int npg = 0; npg < 2; ++npg) {
            uint2 bh[2][2][8];
#pragma unroll
            for (int p = 0; p < 2; ++p)
#pragma unroll
                for (int nt = 0; nt < 2; ++nt) {
                    const int np = npg * 2 + p;
                    const u32 lb = (u32)((((np * 4 + w_) * 2 + nt) * 8) * 64 + lane * 2);
#pragma unroll
                    for (int ks = 0; ks < 8; ++ks)
                        bh[p][nt][ks] = __ldg((const uint2*)(g3h + lb + ks * 64));
                }

            float rm[2][2][2];
#pragma unroll
            for (int p = 0; p < 2; ++p)
#pragma unroll
                for (int nt = 0; nt < 2; ++nt) {
                    rm[p][nt][0] = -3.0e38f; rm[p][nt][1] = -3.0e38f;
                }

#pragma unroll
            for (int mt = 0; mt < 4; ++mt) {
                u32 a[8][4];
#pragma unroll
                for (int ks = 0; ks < 8; ++ks) {
                    const u32 aoff = (u32)(((mt * 16 + lm_row) * H2ST + ks * 8 + lm_col) * 4);
                    ldsm_x4(a[ks][0], a[ks][1], a[ks][2], a[ks][3], h2s_u + aoff);
                }
#pragma unroll
                for (int p = 0; p < 2; ++p)
#pragma unroll
                    for (int nt = 0; nt < 2; ++nt) {
                        float acc[4] = { 0.0f, 0.0f, 0.0f, 0.0f };
#pragma unroll
                        for (int ks = 0; ks < 8; ++ks)
                            mma_f16(acc, a[ks][0], a[ks][1], a[ks][2], a[ks][3],
                                    bh[p][nt][ks].x, bh[p][nt][ks].y);
                        rm[p][nt][0] = fmaxf(rm[p][nt][0], fmaxf(acc[0], acc[2]));
                        rm[p][nt][1] = fmaxf(rm[p][nt][1], fmaxf(acc[1], acc[3]));
                    }
            }

#pragma unroll
            for (int p = 0; p < 2; ++p)
#pragma unroll
                for (int nt = 0; nt < 2; ++nt)
#pragma unroll
                    for (int j = 0; j < 2; ++j) {
                        float m = rm[p][nt][j];
                        m = fmaxf(m, __shfl_xor_sync(0xffffffffu, m, 4));
                        m = fmaxf(m, __shfl_xor_sync(0xffffffffu, m, 8));
                        m = fmaxf(m, __shfl_xor_sync(0xffffffffu, m, 16));
                        if (lane < 4) {
                            const int col = (npg * 2 + p) * 64 + w_ * 16 + nt * 8 + 2 * lane + j;
                            if (hf == 0) feat_s[col] = m;
                            else         feat_s[col] = fmaxf(feat_s[col], m) + __ldg(b3 + col);
                        }
                    }
        }
    }
    __syncthreads();

    if (t < EMB) {
        float acc = __ldg(oeb + t);
#pragma unroll 4
        for (int k = 0; k < 256; k += 4) {
            const float4 f = *(const float4*)&feat_s[k];
            acc = fmaf(f.x, __ldg(oew + (size_t)(k + 0) * EMB + t), acc);
            acc = fmaf(f.y, __ldg(oew + (size_t)(k + 1) * EMB + t), acc);
            acc = fmaf(f.z, __ldg(oew + (size_t)(k + 2) * EMB + t), acc);
            acc = fmaf(f.w, __ldg(oew + (size_t)(k + 3) * EMB + t), acc);
        }
        out[(size_t)n * OUTW + EMB + t] = acc;
    }
}

// ---------------------------------------------------------------------------
// Node branch mma: block = 32 output rows, 128 threads.
//  gather -> x fp16 in shared; L1/L2 = fp16 mma (warp owns 64 cols, K=256);
//  se (256->100 padded 104) = fp16 mma with col guards.
// ---------------------------------------------------------------------------
__device__ __forceinline__ void node_layer(
    u32 src_u, u32* dst, const u32* __restrict__ frags,
    const float* __restrict__ bias, int w_, int lane, bool relu_)
{
    const int lm_row = lane & 15;
    const int lm_col = (lane >> 4) << 2;

    float acc[2][8][4];
#pragma unroll
    for (int nt = 0; nt < 8; ++nt) {
        const float2 bb = __ldg((const float2*)(bias + w_ * 64 + nt * 8 + 2 * (lane & 3)));
#pragma unroll
        for (int mt = 0; mt < 2; ++mt) {
            acc[mt][nt][0] = bb.x; acc[mt][nt][1] = bb.y;
            acc[mt][nt][2] = bb.x; acc[mt][nt][3] = bb.y;
        }
    }
#pragma unroll
    for (int kc = 0; kc < 4; ++kc) {
        u32 a[2][4][4];
#pragma unroll
        for (int mt = 0; mt < 2; ++mt)
#pragma unroll
            for (int ksl = 0; ksl < 4; ++ksl) {
                const u32 aoff = (u32)(((mt * 16 + lm_row) * NST + (kc * 4 + ksl) * 8 + lm_col) * 4);
                ldsm_x4(a[mt][ksl][0], a[mt][ksl][1], a[mt][ksl][2], a[mt][ksl][3], src_u + aoff);
            }
#pragma unroll
        for (int nt = 0; nt < 8; ++nt) {
#pragma unroll
            for (int ksl = 0; ksl < 4; ++ksl) {
                const int L = (w_ * 8 + nt) * 16 + kc * 4 + ksl;
                const uint2 b = __ldg((const uint2*)(frags + L * 64 + lane * 2));
                mma_f16(acc[0][nt], a[0][ksl][0], a[0][ksl][1], a[0][ksl][2], a[0][ksl][3], b.x, b.y);
                mma_f16(acc[1][nt], a[1][ksl][0], a[1][ksl][1], a[1][ksl][2], a[1][ksl][3], b.x, b.y);
            }
        }
    }
#pragma unroll
    for (int nt = 0; nt < 8; ++nt)
#pragma unroll
        for (int mt = 0; mt < 2; ++mt) {
            float c0 = acc[mt][nt][0], c1 = acc[mt][nt][1];
            float c2 = acc[mt][nt][2], c3 = acc[mt][nt][3];
            if (relu_) {
                c0 = fmaxf(c0, 0.0f); c1 = fmaxf(c1, 0.0f);
                c2 = fmaxf(c2, 0.0f); c3 = fmaxf(c3, 0.0f);
            }
            const int r0 = mt * 16 + (lane >> 2);
            const int wd = w_ * 32 + nt * 4 + (lane & 3);
            __half2 p0 = __floats2half2_rn(c0, c1);
            __half2 p1 = __floats2half2_rn(c2, c3);
            dst[r0 * NST + wd]       = *(u32*)&p0;
            dst[(r0 + 8) * NST + wd] = *(u32*)&p1;
        }
}

__global__ __launch_bounds__(128) void node_branch_kernel(
    const float* __restrict__ srcf,
    const float* __restrict__ reff,
    const void*  __restrict__ counts_raw,
    const float* __restrict__ b1, const float* __restrict__ b2,
    const float* __restrict__ seb,
    float* __restrict__ out)
{
    __shared__ u32 xs[32 * NST];   // 16896 B
    __shared__ u32 hs[32 * NST];
    __shared__ int srow[32];
    __shared__ int sflag[32];

    const u32 xs_u = smem_u32(xs);
    const u32 hs_u = smem_u32(hs);

    const int t = threadIdx.x;
    const int w_ = t >> 5, lane = t & 31;
    const long long o0 = (long long)blockIdx.x * 32;

    if (t < 32) {
        const int* c32 = (const int*)counts_raw;
        const bool is64 = (c32[1] == 0 && c32[3] == 0);
        const long long o = o0 + t;
        long long cum = 0, ssum = 0, rsum = 0, idx = 0;
        int flag = 0;
        for (int b = 0; b < NB; ++b) {
            long long sc, rc;
            if (is64) { sc = ((const long long*)counts_raw)[2 * b]; rc = ((const long long*)counts_raw)[2 * b + 1]; }
            else      { sc = c32[2 * b]; rc = c32[2 * b + 1]; }
            const long long tot = sc + rc;
            if (o < cum + tot) {
                const long long off = o - cum;
                if (off < sc) { flag = 0; idx = ssum + off; }
                else          { flag = 1; idx = rsum + (off - sc); }
                break;
            }
            cum += tot; ssum += sc; rsum += rc;
        }
        srow[t] = (int)idx; sflag[t] = flag;
    }
    __syncthreads();

    // load x (32 rows x 256) as fp16
    {
        const int r = t >> 2, q = t & 3;
        const float* base = sflag[r] ? reff : srcf;
        const float* rowp = base + (size_t)srow[r] * FEAT + q * 64;
        u32* dst = &xs[r * NST + q * 32];
#pragma unroll
        for (int i = 0; i < 16; ++i) {
            const float4 f = __ldg((const float4*)(rowp + i * 4));
            __half2 h0 = __floats2half2_rn(f.x, f.y);
            __half2 h1 = __floats2half2_rn(f.z, f.w);
            dst[i * 2]     = *(u32*)&h0;
            dst[i * 2 + 1] = *(u32*)&h1;
        }
    }
    __syncthreads();

    node_layer(xs_u, hs, g_n1, b1, w_, lane, true);    // h = relu(x@W1+b1)
    __syncthreads();
    node_layer(hs_u, xs, g_n2, b2, w_, lane, false);   // e = h@W2+b2
    __syncthreads();

    // se: e(32x256) @ se_w(256x100), nt tiles 0..12 distributed over warps
    {
        const int lm_row = lane & 15;
        const int lm_col = (lane >> 4) << 2;
#pragma unroll 1
        for (int nt = w_; nt < 13; nt += 4) {
            const int cb = nt * 8 + 2 * (lane & 3);
            const float bb0 = (cb     < EMB) ? __ldg(seb + cb)     : 0.0f;
            const float bb1 = (cb + 1 < EMB) ? __ldg(seb + cb + 1) : 0.0f;
            float acc[2][4];
#pragma unroll
            for (int mt = 0; mt < 2; ++mt) {
                acc[mt][0] = bb0; acc[mt][1] = bb1;
                acc[mt][2] = bb0; acc[mt][3] = bb1;
            }
#pragma unroll
            for (int ks = 0; ks < 16; ++ks) {
                const uint2 b = __ldg((const uint2*)(g_se + (nt * 16 + ks) * 64 + lane * 2));
#pragma unroll
                for (int mt = 0; mt < 2; ++mt) {
                    const u32 aoff = (u32)(((mt * 16 + lm_row) * NST + ks * 8 + lm_col) * 4);
                    u32 a0, a1, a2, a3;
                    ldsm_x4(a0, a1, a2, a3, xs_u + aoff);
                    mma_f16(acc[mt], a0, a1, a2, a3, b.x, b.y);
                }
            }
#pragma unroll
            for (int mt = 0; mt < 2; ++mt) {
                const int r0 = mt * 16 + (lane >> 2);
                if (cb < EMB) {
                    out[(size_t)(o0 + r0) * OUTW + cb]     = acc[mt][0];
                    out[(size_t)(o0 + r0 + 8) * OUTW + cb] = acc[mt][2];
                }
                if (cb + 1 < EMB) {
                    out[(size_t)(o0 + r0) * OUTW + cb + 1]     = acc[mt][1];
                    out[(size_t)(o0 + r0 + 8) * OUTW + cb + 1] = acc[mt][3];
                }
            }
        }
    }
}

extern "C" void kernel_launch(void* const* d_in, const int* in_sizes, int n_in,
                              void* d_out, int out_size)
{
    const float* pts    = (const float*)d_in[0];
    const float* srcf   = (const float*)d_in[1];
    const float* reff   = (const float*)d_in[2];
    const void*  counts = d_in[3];
    const float* sg_w1  = (const float*)d_in[6];
    const float* sg_b1  = (const float*)d_in[7];
    const float* sg_w2  = (const float*)d_in[8];
    const float* sg_b2  = (const float*)d_in[9];
    const float* se_w   = (const float*)d_in[10];
    const float* se_b   = (const float*)d_in[11];
    const float* p_w1   = (const float*)d_in[12];
    const float* p_b1   = (const float*)d_in[13];
    const float* p_w2   = (const float*)d_in[14];
    const float* p_b2   = (const float*)d_in[15];
    const float* p_w3   = (const float*)d_in[16];
    const float* p_b3   = (const float*)d_in[17];
    const float* oe_w   = (const float*)d_in[18];
    const float* oe_b   = (const float*)d_in[19];
    float* out = (float*)d_out;

    frag_kernel<<<388, 128>>>(p_w2, p_w3, sg_w1, sg_w2, se_w);
    node_branch_kernel<<<N_TOT / 32, 128>>>(srcf, reff, counts,
                                            sg_b1, sg_b2, se_b, out);
    point_branch_kernel<<<N_TOT, 128>>>(pts, p_w1, p_b1, p_b2, p_b3,
                                        oe_w, oe_b, out);
}

// round 12
// speedup vs baseline: 9.0106x; 1.2073x over previous
#include <cuda_runtime.h>
#include <cuda_fp16.h>
#include <stdint.h>

#define NB    16
#define N_TOT 16384
#define PPT   128
#define FEAT  256
#define EMB   100
#define OUTW  200

typedef unsigned long long u64;
typedef unsigned int u32;

#define LO_SCALE 2048.0f
#define LO_INV   4.8828125e-4f

// ---------------- mma / ldmatrix (portable ISA) ----------------
__device__ __forceinline__ void mma_f16(float* c,
                                        u32 a0, u32 a1, u32 a2, u32 a3,
                                        u32 b0, u32 b1) {
    asm("mma.sync.aligned.m16n8k16.row.col.f32.f16.f16.f32 "
        "{%0,%1,%2,%3}, {%4,%5,%6,%7}, {%8,%9}, {%0,%1,%2,%3};"
        : "+f"(c[0]), "+f"(c[1]), "+f"(c[2]), "+f"(c[3])
        : "r"(a0), "r"(a1), "r"(a2), "r"(a3), "r"(b0), "r"(b1));
}
__device__ __forceinline__ void ldsm_x4(u32& r0, u32& r1, u32& r2, u32& r3, u32 saddr) {
    asm volatile("ldmatrix.sync.aligned.m8n8.x4.shared.b16 {%0,%1,%2,%3}, [%4];"
                 : "=r"(r0), "=r"(r1), "=r"(r2), "=r"(r3) : "r"(saddr));
}
__device__ __forceinline__ u32 smem_u32(const void* p) {
    u32 a; asm("{ .reg .u64 t; cvta.to.shared.u64 t, %1; cvt.u32.u64 %0, t; }" : "=r"(a) : "l"(p));
    return a;
}
__device__ __forceinline__ void split2f(float x0, float x1, u32& hi, u32& lo) {
    __half2 h = __floats2half2_rn(x0, x1);
    __half2 l = __floats2half2_rn((x0 - __low2float(h))  * LO_SCALE,
                                  (x1 - __high2float(h)) * LO_SCALE);
    hi = *(u32*)&h; lo = *(u32*)&l;
}

#define H1ST 36   // point h1 rows: 32 words (fp16x2) + 4 pad
#define H2ST 68   // point h2 rows: 64 words + 4 pad
#define NST  132  // node rows: 128 words + 4 pad

// --------- precomputed fp16 B-fragments (coalesced per group L) ----------
__device__ u32 g3h[256 * 64];    // point W3: L = ((np*4+w)*2+nt)*8 + ks
__device__ u32 g2h[64 * 64];     // point W2: L = (w*4+nt)*4 + ks
__device__ u32 g_n1h[512 * 64];  // node sg_w1 hi: L = ntg*16 + ks
__device__ u32 g_n1l[512 * 64];  // node sg_w1 lo (scaled)
__device__ u32 g_n2h[512 * 64];
__device__ u32 g_n2l[512 * 64];
__device__ u32 g_seh[208 * 64];  // se_w: L = nt*16 + ks (col<100 else 0)
__device__ u32 g_sel[208 * 64];

__global__ void frag_kernel(const float* __restrict__ pw2, const float* __restrict__ pw3,
                            const float* __restrict__ n1,  const float* __restrict__ n2,
                            const float* __restrict__ sew)
{
    const int bid = blockIdx.x;
    if (bid < 64) {                      // point W3 (single fp16)
        const int gid = bid * 128 + threadIdx.x;
        const int L = gid >> 5, lane = gid & 31;
        const int ks = L & 7, nt = (L >> 3) & 1, w = (L >> 4) & 3, np = L >> 6;
        const int gcol = np * 64 + w * 16 + nt * 8 + (lane >> 2);
        const int k0 = 16 * ks + 2 * (lane & 3);
        __half2 h0 = __floats2half2_rn(pw3[(size_t)k0 * 256 + gcol],
                                       pw3[(size_t)(k0 + 1) * 256 + gcol]);
        __half2 h1 = __floats2half2_rn(pw3[(size_t)(k0 + 8) * 256 + gcol],
                                       pw3[(size_t)(k0 + 9) * 256 + gcol]);
        g3h[L * 64 + lane * 2]     = *(u32*)&h0;
        g3h[L * 64 + lane * 2 + 1] = *(u32*)&h1;
    } else if (bid < 80) {               // point W2 (single fp16)
        const int gid = (bid - 64) * 128 + threadIdx.x;
        const int L = gid >> 5, lane = gid & 31;
        const int ks = L & 3, nt = (L >> 2) & 3, w = L >> 4;
        const int gcol = w * 32 + nt * 8 + (lane >> 2);
        const int k0 = 16 * ks + 2 * (lane & 3);
        __half2 h0 = __floats2half2_rn(pw2[(size_t)k0 * 128 + gcol],
                                       pw2[(size_t)(k0 + 1) * 128 + gcol]);
        __half2 h1 = __floats2half2_rn(pw2[(size_t)(k0 + 8) * 128 + gcol],
                                       pw2[(size_t)(k0 + 9) * 128 + gcol]);
        g2h[L * 64 + lane * 2]     = *(u32*)&h0;
        g2h[L * 64 + lane * 2 + 1] = *(u32*)&h1;
    } else if (bid < 336) {              // node sg_w1/sg_w2 (hi/lo)
        const int gid = (bid - 80) * 128 + threadIdx.x;
        const int sel = gid >= 16384;
        const float* w = sel ? n2 : n1;
        u32* dh = sel ? g_n2h : g_n1h;
        u32* dl = sel ? g_n2l : g_n1l;
        const int g = gid & 16383;
        const int L = g >> 5, lane = g & 31;
        const int ks = L & 15, ntg = L >> 4;
        const int col = ntg * 8 + (lane >> 2);
        const int k0 = 16 * ks + 2 * (lane & 3);
        u32 h0, l0, h1, l1;
        split2f(w[(size_t)k0 * 256 + col],       w[(size_t)(k0 + 1) * 256 + col], h0, l0);
        split2f(w[(size_t)(k0 + 8) * 256 + col], w[(size_t)(k0 + 9) * 256 + col], h1, l1);
        dh[L * 64 + lane * 2]     = h0;
        dh[L * 64 + lane * 2 + 1] = h1;
        dl[L * 64 + lane * 2]     = l0;
        dl[L * 64 + lane * 2 + 1] = l1;
    } else {                             // se_w (hi/lo)
        const int gid = (bid - 336) * 128 + threadIdx.x;
        if (gid < 6656) {
            const int L = gid >> 5, lane = gid & 31;
            const int ks = L & 15, nt = L >> 4;
            const int col = nt * 8 + (lane >> 2);
            const int k0 = 16 * ks + 2 * (lane & 3);
            const bool ok = (col < EMB);
            u32 h0, l0, h1, l1;
            split2f(ok ? sew[(size_t)k0 * EMB + col] : 0.0f,
                    ok ? sew[(size_t)(k0 + 1) * EMB + col] : 0.0f, h0, l0);
            split2f(ok ? sew[(size_t)(k0 + 8) * EMB + col] : 0.0f,
                    ok ? sew[(size_t)(k0 + 9) * EMB + col] : 0.0f, h1, l1);
            g_seh[L * 64 + lane * 2]     = h0;
            g_seh[L * 64 + lane * 2 + 1] = h1;
            g_sel[L * 64 + lane * 2]     = l0;
            g_sel[L * 64 + lane * 2 + 1] = l1;
        }
    }
}

// Dynamic smem for point kernel: h2(8704) + h1(4608) + feat(256) words
#define P_DSM_WORDS (8704 + 4608 + 256)
#define P_DSM_BYTES (P_DSM_WORDS * 4)

// ---------------------------------------------------------------------------
// Point branch: block = one object, 128 threads, SINGLE pass (all 128 points).
// ---------------------------------------------------------------------------
__global__ __launch_bounds__(128, 4) void point_branch_kernel(
    const float* __restrict__ pts,
    const float* __restrict__ w1, const float* __restrict__ b1,
    const float* __restrict__ b2, const float* __restrict__ b3,
    const float* __restrict__ oew, const float* __restrict__ oeb,
    float* __restrict__ out)
{
    extern __shared__ u32 dsm[];
    u32* h2s = dsm;                       // 128 x H2ST
    u32* h1s = dsm + 8704;                // 128 x H1ST
    float* feat_s = (float*)(dsm + 8704 + 4608);

    const u32 h2s_u = smem_u32(h2s);
    const u32 h1s_u = smem_u32(h1s);

    const int n    = blockIdx.x;
    const int t    = threadIdx.x;
    const int w_   = t >> 5;
    const int lane = t & 31;

    const int lm_row = lane & 15;
    const int lm_col = (lane >> 4) << 2;

    // ================= layer 1: all 128 points -> h1 fp16 ===================
#pragma unroll
    for (int pg = 0; pg < 4; ++pg) {
        const int pl = t & 31;
        const int j0 = (t >> 5) * 16;
        const int row = pg * 32 + pl;
        const size_t pb = ((size_t)n * PPT + row) * 3;
        const float x = pts[pb + 0], y = pts[pb + 1], z = pts[pb + 2];
        u32 hw[8];
#pragma unroll
        for (int q = 0; q < 8; ++q) {
            const int jj = j0 + 2 * q;
            float r0 = fmaf(x, __ldg(w1 + jj),     fmaf(y, __ldg(w1 + 64 + jj),     fmaf(z, __ldg(w1 + 128 + jj),     __ldg(b1 + jj))));
            float r1 = fmaf(x, __ldg(w1 + jj + 1), fmaf(y, __ldg(w1 + 64 + jj + 1), fmaf(z, __ldg(w1 + 128 + jj + 1), __ldg(b1 + jj + 1))));
            __half2 h = __floats2half2_rn(fmaxf(r0, 0.0f), fmaxf(r1, 0.0f));
            hw[q] = *(u32*)&h;
        }
        const int wb = row * H1ST + (j0 >> 1);
        *(uint4*)&h1s[wb]     = make_uint4(hw[0], hw[1], hw[2], hw[3]);
        *(uint4*)&h1s[wb + 4] = make_uint4(hw[4], hw[5], hw[6], hw[7]);
    }
    __syncthreads();

    // ================= layer 2: fp16 mma, mt 0..8 ===========================
    {
        uint2 bh[4][4];
        float2 bb[4];
#pragma unroll
        for (int nt = 0; nt < 4; ++nt) {
            const u32 lb = (u32)(((w_ * 4 + nt) * 4) * 64 + lane * 2);
#pragma unroll
            for (int ks = 0; ks < 4; ++ks)
                bh[nt][ks] = __ldg((const uint2*)(g2h + lb + ks * 64));
            bb[nt] = __ldg((const float2*)(b2 + w_ * 32 + nt * 8 + 2 * (lane & 3)));
        }

#pragma unroll
        for (int mt = 0; mt < 8; ++mt) {
            u32 a[4][4];
#pragma unroll
            for (int ks = 0; ks < 4; ++ks) {
                const u32 aoff = (u32)(((mt * 16 + lm_row) * H1ST + ks * 8 + lm_col) * 4);
                ldsm_x4(a[ks][0], a[ks][1], a[ks][2], a[ks][3], h1s_u + aoff);
            }
#pragma unroll
            for (int nt = 0; nt < 4; ++nt) {
                float acc[4] = { bb[nt].x, bb[nt].y, bb[nt].x, bb[nt].y };
#pragma unroll
                for (int ks = 0; ks < 4; ++ks)
                    mma_f16(acc, a[ks][0], a[ks][1], a[ks][2], a[ks][3],
                            bh[nt][ks].x, bh[nt][ks].y);
                const int r0 = mt * 16 + (lane >> 2);
                const int wd = w_ * 16 + nt * 4 + (lane & 3);
                __half2 p0 = __floats2half2_rn(fmaxf(acc[0], 0.0f), fmaxf(acc[1], 0.0f));
                __half2 p1 = __floats2half2_rn(fmaxf(acc[2], 0.0f), fmaxf(acc[3], 0.0f));
                h2s[r0 * H2ST + wd]       = *(u32*)&p0;
                h2s[(r0 + 8) * H2ST + wd] = *(u32*)&p1;
            }
        }
    }
    __syncthreads();

    // ================= layer 3: fp16 mma, np pairs, mt 0..8 =================
#pragma unroll 1
    for (int npg = 0; npg < 2; ++npg) {
        uint2 bh[2][2][8];
#pragma unroll
        for (int p = 0; p < 2; ++p)
#pragma unroll
            for (int nt = 0; nt < 2; ++nt) {
                const int np = npg * 2 + p;
                const u32 lb = (u32)((((np * 4 + w_) * 2 + nt) * 8) * 64 + lane * 2);
#pragma unroll
                for (int ks = 0; ks < 8; ++ks)
                    bh[p][nt][ks] = __ldg((const uint2*)(g3h + lb + ks * 64));
            }

        float rm[2][2][2];
#pragma unroll
        for (int p = 0; p < 2; ++p)
#pragma unroll
            for (int nt = 0; nt < 2; ++nt) {
                rm[p][nt][0] = -3.0e38f; rm[p][nt][1] = -3.0e38f;
            }

#pragma unroll
        for (int mt = 0; mt < 8; ++mt) {
            u32 a[8][4];
#pragma unroll
            for (int ks = 0; ks < 8; ++ks) {
                const u32 aoff = (u32)(((mt * 16 + lm_row) * H2ST + ks * 8 + lm_col) * 4);
                ldsm_x4(a[ks][0], a[ks][1], a[ks][2], a[ks][3], h2s_u + aoff);
            }
#pragma unroll
            for (int p = 0; p < 2; ++p)
#pragma unroll
                for (int nt = 0; nt < 2; ++nt) {
                    float acc[4] = { 0.0f, 0.0f, 0.0f, 0.0f };
#pragma unroll
                    for (int ks = 0; ks < 8; ++ks)
                        mma_f16(acc, a[ks][0], a[ks][1], a[ks][2], a[ks][3],
                                bh[p][nt][ks].x, bh[p][nt][ks].y);
                    rm[p][nt][0] = fmaxf(rm[p][nt][0], fmaxf(acc[0], acc[2]));
                    rm[p][nt][1] = fmaxf(rm[p][nt][1], fmaxf(acc[1], acc[3]));
                }
        }

#pragma unroll
        for (int p = 0; p < 2; ++p)
#pragma unroll
            for (int nt = 0; nt < 2; ++nt)
#pragma unroll
                for (int j = 0; j < 2; ++j) {
                    float m = rm[p][nt][j];
                    m = fmaxf(m, __shfl_xor_sync(0xffffffffu, m, 4));
                    m = fmaxf(m, __shfl_xor_sync(0xffffffffu, m, 8));
                    m = fmaxf(m, __shfl_xor_sync(0xffffffffu, m, 16));
                    if (lane < 4) {
                        const int col = (npg * 2 + p) * 64 + w_ * 16 + nt * 8 + 2 * lane + j;
                        feat_s[col] = m + __ldg(b3 + col);
                    }
                }
    }
    __syncthreads();

    // ---- pt_out = feat @ oe_w + oe_b
    if (t < EMB) {
        float acc = __ldg(oeb + t);
#pragma unroll 4
        for (int k = 0; k < 256; k += 4) {
            const float4 f = *(const float4*)&feat_s[k];
            acc = fmaf(f.x, __ldg(oew + (size_t)(k + 0) * EMB + t), acc);
            acc = fmaf(f.y, __ldg(oew + (size_t)(k + 1) * EMB + t), acc);
            acc = fmaf(f.z, __ldg(oew + (size_t)(k + 2) * EMB + t), acc);
            acc = fmaf(f.w, __ldg(oew + (size_t)(k + 3) * EMB + t), acc);
        }
        out[(size_t)n * OUTW + EMB + t] = acc;
    }
}

// ---------------------------------------------------------------------------
// Node branch: block = 16 rows, 128 threads, hi/lo 3-product fp16 splits.
// ---------------------------------------------------------------------------
__device__ __forceinline__ void node_layer(
    u32 sh_u, u32 sl_u, u32* dh, u32* dl,
    const u32* __restrict__ fh, const u32* __restrict__ fl,
    const float* __restrict__ bias, int w_, int lane, bool relu_)
{
    const int lm_row = lane & 15;
    const int lm_col = (lane >> 4) << 2;

    float acc_h[8][4], acc_m[8][4];
#pragma unroll
    for (int nt = 0; nt < 8; ++nt)
#pragma unroll
        for (int q = 0; q < 4; ++q) { acc_h[nt][q] = 0.0f; acc_m[nt][q] = 0.0f; }

#pragma unroll
    for (int kc = 0; kc < 4; ++kc) {
        u32 ah[4][4], al[4][4];
#pragma unroll
        for (int ksl = 0; ksl < 4; ++ksl) {
            const u32 aoff = (u32)((lm_row * NST + (kc * 4 + ksl) * 8 + lm_col) * 4);
            ldsm_x4(ah[ksl][0], ah[ksl][1], ah[ksl][2], ah[ksl][3], sh_u + aoff);
            ldsm_x4(al[ksl][0], al[ksl][1], al[ksl][2], al[ksl][3], sl_u + aoff);
        }
#pragma unroll
        for (int nt = 0; nt < 8; ++nt) {
#pragma unroll
            for (int ksl = 0; ksl < 4; ++ksl) {
                const int L = (w_ * 8 + nt) * 16 + kc * 4 + ksl;
                const uint2 bhv = __ldg((const uint2*)(fh + L * 64 + lane * 2));
                const uint2 blv = __ldg((const uint2*)(fl + L * 64 + lane * 2));
                mma_f16(acc_h[nt], ah[ksl][0], ah[ksl][1], ah[ksl][2], ah[ksl][3], bhv.x, bhv.y);
                mma_f16(acc_m[nt], ah[ksl][0], ah[ksl][1], ah[ksl][2], ah[ksl][3], blv.x, blv.y);
                mma_f16(acc_m[nt], al[ksl][0], al[ksl][1], al[ksl][2], al[ksl][3], bhv.x, bhv.y);
            }
        }
    }
#pragma unroll
    for (int nt = 0; nt < 8; ++nt) {
        const float2 bb = __ldg((const float2*)(bias + w_ * 64 + nt * 8 + 2 * (lane & 3)));
        float c0 = acc_h[nt][0] + LO_INV * acc_m[nt][0] + bb.x;
        float c1 = acc_h[nt][1] + LO_INV * acc_m[nt][1] + bb.y;
        float c2 = acc_h[nt][2] + LO_INV * acc_m[nt][2] + bb.x;
        float c3 = acc_h[nt][3] + LO_INV * acc_m[nt][3] + bb.y;
        if (relu_) {
            c0 = fmaxf(c0, 0.0f); c1 = fmaxf(c1, 0.0f);
            c2 = fmaxf(c2, 0.0f); c3 = fmaxf(c3, 0.0f);
        }
        const int r0 = lane >> 2;
        const int wd = w_ * 32 + nt * 4 + (lane & 3);
        u32 h0, l0, h1, l1;
        split2f(c0, c1, h0, l0);
        split2f(c2, c3, h1, l1);
        dh[r0 * NST + wd]       = h0;
        dl[r0 * NST + wd]       = l0;
        dh[(r0 + 8) * NST + wd] = h1;
        dl[(r0 + 8) * NST + wd] = l1;
    }
}

__global__ __launch_bounds__(128) void node_branch_kernel(
    const float* __restrict__ srcf,
    const float* __restrict__ reff,
    const void*  __restrict__ counts_raw,
    const float* __restrict__ b1, const float* __restrict__ b2,
    const float* __restrict__ seb,
    float* __restrict__ out)
{
    __shared__ u32 xs_h[16 * NST];
    __shared__ u32 xs_l[16 * NST];
    __shared__ u32 hs_h[16 * NST];
    __shared__ u32 hs_l[16 * NST];
    __shared__ int srow[16];
    __shared__ int sflag[16];

    const u32 xsh_u = smem_u32(xs_h), xsl_u = smem_u32(xs_l);
    const u32 hsh_u = smem_u32(hs_h), hsl_u = smem_u32(hs_l);

    const int t = threadIdx.x;
    const int w_ = t >> 5, lane = t & 31;
    const long long o0 = (long long)blockIdx.x * 16;

    if (t < 16) {
        const int* c32 = (const int*)counts_raw;
        const bool is64 = (c32[1] == 0 && c32[3] == 0);
        const long long o = o0 + t;
        long long cum = 0, ssum = 0, rsum = 0, idx = 0;
        int flag = 0;
        for (int b = 0; b < NB; ++b) {
            long long sc, rc;
            if (is64) { sc = ((const long long*)counts_raw)[2 * b]; rc = ((const long long*)counts_raw)[2 * b + 1]; }
            else      { sc = c32[2 * b]; rc = c32[2 * b + 1]; }
            const long long tot = sc + rc;
            if (o < cum + tot) {
                const long long off = o - cum;
                if (off < sc) { flag = 0; idx = ssum + off; }
                else          { flag = 1; idx = rsum + (off - sc); }
                break;
            }
            cum += tot; ssum += sc; rsum += rc;
        }
        srow[t] = (int)idx; sflag[t] = flag;
    }
    __syncthreads();

    // gather 16 rows x 256 -> hi/lo fp16
    {
        const int r = t >> 3, q = t & 7;
        const float* base = sflag[r] ? reff : srcf;
        const float* rowp = base + (size_t)srow[r] * FEAT + q * 32;
        u32* dh = &xs_h[r * NST + q * 16];
        u32* dl = &xs_l[r * NST + q * 16];
#pragma unroll
        for (int i = 0; i < 8; ++i) {
            const float4 f = __ldg((const float4*)(rowp + i * 4));
            u32 h0, l0, h1, l1;
            split2f(f.x, f.y, h0, l0);
            split2f(f.z, f.w, h1, l1);
            dh[i * 2]     = h0; dh[i * 2 + 1] = h1;
            dl[i * 2]     = l0; dl[i * 2 + 1] = l1;
        }
    }
    __syncthreads();

    node_layer(xsh_u, xsl_u, hs_h, hs_l, g_n1h, g_n1l, b1, w_, lane, true);
    __syncthreads();
    node_layer(hsh_u, hsl_u, xs_h, xs_l, g_n2h, g_n2l, b2, w_, lane, false);
    __syncthreads();

    // se: e(16x256) @ se_w(256x100), nt tiles 0..12 over 4 warps
    {
        const int lm_row = lane & 15;
        const int lm_col = (lane >> 4) << 2;
#pragma unroll 1
        for (int nt = w_; nt < 13; nt += 4) {
            const int cb = nt * 8 + 2 * (lane & 3);
            float acc_h[4] = {0, 0, 0, 0}, acc_m[4] = {0, 0, 0, 0};
#pragma unroll
            for (int ks = 0; ks < 16; ++ks) {
                const uint2 bhv = __ldg((const uint2*)(g_seh + (nt * 16 + ks) * 64 + lane * 2));
                const uint2 blv = __ldg((const uint2*)(g_sel + (nt * 16 + ks) * 64 + lane * 2));
                const u32 aoff = (u32)((lm_row * NST + ks * 8 + lm_col) * 4);
                u32 a0, a1, a2, a3, c0, c1, c2, c3;
                ldsm_x4(a0, a1, a2, a3, xsh_u + aoff);
                ldsm_x4(c0, c1, c2, c3, xsl_u + aoff);
                mma_f16(acc_h, a0, a1, a2, a3, bhv.x, bhv.y);
                mma_f16(acc_m, a0, a1, a2, a3, blv.x, blv.y);
                mma_f16(acc_m, c0, c1, c2, c3, bhv.x, bhv.y);
            }
            const float bb0 = (cb     < EMB) ? __ldg(seb + cb)     : 0.0f;
            const float bb1 = (cb + 1 < EMB) ? __ldg(seb + cb + 1) : 0.0f;
            const float v0 = acc_h[0] + LO_INV * acc_m[0] + bb0;
            const float v1 = acc_h[1] + LO_INV * acc_m[1] + bb1;
            const float v2 = acc_h[2] + LO_INV * acc_m[2] + bb0;
            const float v3 = acc_h[3] + LO_INV * acc_m[3] + bb1;
            const int r0 = lane >> 2;
            if (cb < EMB) {
                out[(size_t)(o0 + r0) * OUTW + cb]     = v0;
                out[(size_t)(o0 + r0 + 8) * OUTW + cb] = v2;
            }
            if (cb + 1 < EMB) {
                out[(size_t)(o0 + r0) * OUTW + cb + 1]     = v1;
                out[(size_t)(o0 + r0 + 8) * OUTW + cb + 1] = v3;
            }
        }
    }
}

extern "C" void kernel_launch(void* const* d_in, const int* in_sizes, int n_in,
                              void* d_out, int out_size)
{
    const float* pts    = (const float*)d_in[0];
    const float* srcf   = (const float*)d_in[1];
    const float* reff   = (const float*)d_in[2];
    const void*  counts = d_in[3];
    const float* sg_w1  = (const float*)d_in[6];
    const float* sg_b1  = (const float*)d_in[7];
    const float* sg_w2  = (const float*)d_in[8];
    const float* sg_b2  = (const float*)d_in[9];
    const float* se_w   = (const float*)d_in[10];
    const float* se_b   = (const float*)d_in[11];
    const float* p_w1   = (const float*)d_in[12];
    const float* p_b1   = (const float*)d_in[13];
    const float* p_w2   = (const float*)d_in[14];
    const float* p_b2   = (const float*)d_in[15];
    const float* p_w3   = (const float*)d_in[16];
    const float* p_b3   = (const float*)d_in[17];
    const float* oe_w   = (const float*)d_in[18];
    const float* oe_b   = (const float*)d_in[19];
    float* out = (float*)d_out;

    cudaFuncSetAttribute(point_branch_kernel,
                         cudaFuncAttributeMaxDynamicSharedMemorySize, P_DSM_BYTES);

    frag_kernel<<<388, 128>>>(p_w2, p_w3, sg_w1, sg_w2, se_w);
    node_branch_kernel<<<N_TOT / 16, 128>>>(srcf, reff, counts,
                                            sg_b1, sg_b2, se_b, out);
    point_branch_kernel<<<N_TOT, 128, P_DSM_BYTES>>>(pts, p_w1, p_b1, p_b2, p_b3,
                                                     oe_w, oe_b, out);
}